// round 11
// baseline (speedup 1.0000x reference)
#include <cuda_runtime.h>
#include <cuda_bf16.h>
#include <cstdint>

// Problem constants
#define BB 2
#define NN 2048
#define EE 2048
#define HH 16
#define DD 128
#define MTOT (BB * NN)
#define SCALE 0.08838834764831843f

// ---------------------------------------------------------------------------
// Device scratch (allocation-free rule)
// ---------------------------------------------------------------------------
__device__ __nv_bfloat16 g_qh[(size_t)BB * HH * NN * DD];  // Q hi [B,H,N,D]
__device__ __nv_bfloat16 g_ql[(size_t)BB * HH * NN * DD];  // Q lo
__device__ __nv_bfloat16 g_kh[(size_t)BB * HH * NN * DD];  // K hi [B,H,N,D]
__device__ __nv_bfloat16 g_kl[(size_t)BB * HH * NN * DD];  // K lo
__device__ __nv_bfloat16 g_vth[(size_t)BB * HH * DD * NN]; // V hi [B,H,D,N]
__device__ __nv_bfloat16 g_vtl[(size_t)BB * HH * DD * NN]; // V lo [B,H,D,N]

__device__ __nv_bfloat16 s_xh[8388608],  s_xl[8388608];   // x split     [M,K]
__device__ __nv_bfloat16 s_wqh[4194304], s_wql[4194304];  // Wq split    [E,K]
__device__ __nv_bfloat16 s_wkh[8388608], s_wkl[8388608];  // Wkv split   [2E,K]
__device__ __nv_bfloat16 s_woh[4194304], s_wol[4194304];  // Wout split  [E,K]
__device__ __nv_bfloat16 s_ah[8388608],  s_al[8388608];   // attn out split [B,N,E]

// ---------------------------------------------------------------------------
// Helpers
// ---------------------------------------------------------------------------
__device__ __forceinline__ uint32_t smem_u32(const void* p) {
    uint32_t a;
    asm("{ .reg .u64 t; cvta.to.shared.u64 t, %1; cvt.u32.u64 %0, t; }"
        : "=r"(a) : "l"(p));
    return a;
}
__device__ __forceinline__ void cp16(uint32_t dst, const void* src) {
    asm volatile("cp.async.cg.shared.global [%0], [%1], 16;"
                 :: "r"(dst), "l"(src));
}
__device__ __forceinline__ void cp_commit() {
    asm volatile("cp.async.commit_group;");
}
__device__ __forceinline__ uint32_t swz(uint32_t off) {   // SW64 for 64B rows
    return off ^ ((off >> 3) & 0x30);
}
__device__ __forceinline__ void ldmx4(uint32_t* f, uint32_t addr) {
    asm volatile("ldmatrix.sync.aligned.m8n8.x4.shared.b16 {%0,%1,%2,%3}, [%4];"
                 : "=r"(f[0]), "=r"(f[1]), "=r"(f[2]), "=r"(f[3]) : "r"(addr));
}
__device__ __forceinline__ void mma16816(float* c, const uint32_t* a,
                                         uint32_t b0, uint32_t b1) {
    asm volatile(
        "mma.sync.aligned.m16n8k16.row.col.f32.bf16.bf16.f32 "
        "{%0,%1,%2,%3}, {%4,%5,%6,%7}, {%8,%9}, {%0,%1,%2,%3};"
        : "+f"(c[0]), "+f"(c[1]), "+f"(c[2]), "+f"(c[3])
        : "r"(a[0]), "r"(a[1]), "r"(a[2]), "r"(a[3]), "r"(b0), "r"(b1));
}
__device__ __forceinline__ uint32_t packbf(float a, float b) {
    __nv_bfloat162 t = __floats2bfloat162_rn(a, b);
    return *(uint32_t*)&t;
}

// ---------------------------------------------------------------------------
// Split kernel: fp32 -> (hi, lo) bf16
// ---------------------------------------------------------------------------
__global__ __launch_bounds__(256) void split_kernel(
    const float* __restrict__ src, __nv_bfloat16* __restrict__ hi,
    __nv_bfloat16* __restrict__ lo, int n4)
{
    int i = blockIdx.x * blockDim.x + threadIdx.x;
    if (i >= n4) return;
    float4 v = ((const float4*)src)[i];
    float vv[4] = {v.x, v.y, v.z, v.w};
    __nv_bfloat16 h[4], l[4];
#pragma unroll
    for (int j = 0; j < 4; ++j) {
        h[j] = __float2bfloat16(vv[j]);
        l[j] = __float2bfloat16(vv[j] - __bfloat162float(h[j]));
    }
    ((uint2*)hi)[i] = *(const uint2*)h;
    ((uint2*)lo)[i] = *(const uint2*)l;
}

// ---------------------------------------------------------------------------
// bf16-split GEMM via mma.sync: C = A @ W^T
// Term-major MMA issue order (RAW distance 16) to hide HMMA latency.
// MODE 0: Cout fp32 [M,E]
// MODE 1: Q -> g_qh/g_ql bf16 split [B,H,N,D]
// MODE 2: e<E: K -> g_kh/g_kl [B,H,N,D];  e>=E: V -> g_vth/g_vtl [B,H,D,N]
// ---------------------------------------------------------------------------
#define TILE_BYTES 8192
#define STAGE_BYTES (4 * TILE_BYTES)
#define GEMM_SMEM 67584

__device__ __forceinline__ void load_chunk(
    uint32_t stage, const __nv_bfloat16* Ahp, const __nv_bfloat16* Alp,
    const __nv_bfloat16* Whp, const __nv_bfloat16* Wlp,
    int m0, int n0, int k0, int Kdim, int tid)
{
#pragma unroll
    for (int t = 0; t < 2; ++t) {
        const int c = tid + t * 256;
        const int row = c >> 2;
        const int kc = c & 3;
        const uint32_t so = swz((uint32_t)(row * 64 + kc * 16));
        const size_t gA = (size_t)(m0 + row) * Kdim + k0 + kc * 8;
        const size_t gW = (size_t)(n0 + row) * Kdim + k0 + kc * 8;
        cp16(stage + 0 * TILE_BYTES + so, Ahp + gA);
        cp16(stage + 1 * TILE_BYTES + so, Alp + gA);
        cp16(stage + 2 * TILE_BYTES + so, Whp + gW);
        cp16(stage + 3 * TILE_BYTES + so, Wlp + gW);
    }
}

template <int MODE>
__global__ void __launch_bounds__(256) gemm_mma(
    const __nv_bfloat16* __restrict__ Ahp, const __nv_bfloat16* __restrict__ Alp,
    const __nv_bfloat16* __restrict__ Whp, const __nv_bfloat16* __restrict__ Wlp,
    float* __restrict__ Cout, int Kdim)
{
    extern __shared__ char smem[];
    const uint32_t sb = smem_u32(smem);
    const int tid = threadIdx.x;
    const int lane = tid & 31;
    const int w = tid >> 5;
    const int wm = w >> 2;
    const int wn = w & 3;
    const int m0 = blockIdx.y * 128;
    const int n0 = blockIdx.x * 128;

    float acc[4][4][4];
#pragma unroll
    for (int i = 0; i < 4; ++i)
#pragma unroll
        for (int j = 0; j < 4; ++j)
#pragma unroll
            for (int r = 0; r < 4; ++r) acc[i][j][r] = 0.0f;

    const int sel = lane >> 3;
    const int lrow8 = ((sel & 1) << 3) + (lane & 7);
    const int lkc = sel >> 1;

    const int nk = Kdim >> 5;
    load_chunk(sb, Ahp, Alp, Whp, Wlp, m0, n0, 0, Kdim, tid);
    cp_commit();

    for (int kt = 0; kt < nk; ++kt) {
        const int buf = kt & 1;
        const uint32_t stage = sb + buf * STAGE_BYTES;

        if (kt + 1 < nk) {
            load_chunk(sb + (buf ^ 1) * STAGE_BYTES, Ahp, Alp, Whp, Wlp,
                       m0, n0, (kt + 1) << 5, Kdim, tid);
            cp_commit();
            asm volatile("cp.async.wait_group 1;");
        } else {
            asm volatile("cp.async.wait_group 0;");
        }
        __syncthreads();

#pragma unroll
        for (int kk = 0; kk < 2; ++kk) {
            const int kchunk = kk * 2 + lkc;
            uint32_t ah[4][4], al[4][4];
#pragma unroll
            for (int i = 0; i < 4; ++i) {
                const int r = wm * 64 + i * 16 + lrow8;
                const uint32_t off = swz((uint32_t)(r * 64 + kchunk * 16));
                ldmx4(ah[i], stage + 0 * TILE_BYTES + off);
                ldmx4(al[i], stage + 1 * TILE_BYTES + off);
            }
            uint32_t bh[2][4], bl[2][4];
#pragma unroll
            for (int j2 = 0; j2 < 2; ++j2) {
                const int r = wn * 32 + j2 * 16 + lrow8;
                const uint32_t off = swz((uint32_t)(r * 64 + kchunk * 16));
                ldmx4(bh[j2], stage + 2 * TILE_BYTES + off);
                ldmx4(bl[j2], stage + 3 * TILE_BYTES + off);
            }
            // Term-major issue: 16 independent accumulators per term.
#pragma unroll
            for (int i = 0; i < 4; ++i)
#pragma unroll
                for (int j = 0; j < 4; ++j) {
                    const int j2 = j >> 1, jo = j & 1;
                    mma16816(acc[i][j], ah[i], bh[j2][jo], bh[j2][2 + jo]);
                }
#pragma unroll
            for (int i = 0; i < 4; ++i)
#pragma unroll
                for (int j = 0; j < 4; ++j) {
                    const int j2 = j >> 1, jo = j & 1;
                    mma16816(acc[i][j], al[i], bh[j2][jo], bh[j2][2 + jo]);
                }
#pragma unroll
            for (int i = 0; i < 4; ++i)
#pragma unroll
                for (int j = 0; j < 4; ++j) {
                    const int j2 = j >> 1, jo = j & 1;
                    mma16816(acc[i][j], ah[i], bl[j2][jo], bl[j2][2 + jo]);
                }
        }
        __syncthreads();
    }

    // ---- Epilogue ----
    float* Ss = (float*)smem;   // [128][132]
#pragma unroll
    for (int i = 0; i < 4; ++i) {
        const int r = wm * 64 + i * 16 + (lane >> 2);
#pragma unroll
        for (int j = 0; j < 4; ++j) {
            const int cc = wn * 32 + j * 8 + 2 * (lane & 3);
            Ss[r * 132 + cc]           = acc[i][j][0];
            Ss[r * 132 + cc + 1]       = acc[i][j][1];
            Ss[(r + 8) * 132 + cc]     = acc[i][j][2];
            Ss[(r + 8) * 132 + cc + 1] = acc[i][j][3];
        }
    }
    __syncthreads();

    const int b = m0 >> 11;
    const int nbase = m0 & (NN - 1);

    if (MODE == 0) {
#pragma unroll
        for (int it = 0; it < 16; ++it) {
            const int f = it * 256 + tid;
            const int r = f >> 5;
            const int c4 = (f & 31) << 2;
            float4 v = *(const float4*)(Ss + r * 132 + c4);
            *(float4*)(Cout + (size_t)(m0 + r) * EE + n0 + c4) = v;
        }
    } else if (MODE == 1 || (MODE == 2 && n0 < EE)) {
        const int h = (n0 & (EE - 1)) >> 7;
        __nv_bfloat16* dh = (MODE == 1 ? g_qh : g_kh) +
            ((size_t)(b * HH + h) * NN + nbase) * DD;
        __nv_bfloat16* dl = (MODE == 1 ? g_ql : g_kl) +
            ((size_t)(b * HH + h) * NN + nbase) * DD;
#pragma unroll
        for (int it = 0; it < 16; ++it) {
            const int f = it * 256 + tid;
            const int r = f >> 5;
            const int c4 = (f & 31) << 2;
            float4 v = *(const float4*)(Ss + r * 132 + c4);
            float vv[4] = {v.x, v.y, v.z, v.w};
            __nv_bfloat16 hi[4], lo[4];
#pragma unroll
            for (int q = 0; q < 4; ++q) {
                hi[q] = __float2bfloat16(vv[q]);
                lo[q] = __float2bfloat16(vv[q] - __bfloat162float(hi[q]));
            }
            *(uint2*)(dh + (size_t)r * DD + c4) = *(const uint2*)hi;
            *(uint2*)(dl + (size_t)r * DD + c4) = *(const uint2*)lo;
        }
    } else {
        // V -> g_vth/g_vtl bf16 split, transposed [B,H,D,N]
        const int h2 = (n0 - EE) >> 7;
        const int col = tid >> 1;
        const int rh2 = tid & 1;
        const size_t dof = ((size_t)(b * HH + h2) * DD + col) * NN +
                           nbase + (rh2 << 6);
        __nv_bfloat16* dsth = g_vth + dof;
        __nv_bfloat16* dstl = g_vtl + dof;
#pragma unroll
        for (int i = 0; i < 16; ++i) {
            const int r = (rh2 << 6) + (i << 2);
            __nv_bfloat16 vh4[4], vl4[4];
#pragma unroll
            for (int q = 0; q < 4; ++q) {
                const float f = Ss[(r + q) * 132 + col];
                vh4[q] = __float2bfloat16(f);
                vl4[q] = __float2bfloat16(f - __bfloat162float(vh4[q]));
            }
            *(uint2*)(dsth + (i << 2)) = *(const uint2*)vh4;
            *(uint2*)(dstl + (i << 2)) = *(const uint2*)vl4;
        }
    }
}

// ---------------------------------------------------------------------------
// Flash attention v2: mma.sync, 3-term splits for QK^T AND PV,
// term-major MMA issue order for latency hiding.
// Br=128 (8 warps x 16 rows), Bc=64, D=128.
// Smem: Qh,Ql [128x272B] | 2 stages of {Kh,Kl 64x272B; Vh,Vl 128x144B}
// ---------------------------------------------------------------------------
#define FQ_BYTES 34816              // 128*272
#define FK_BYTES 17408              // 64*272
#define FV_BYTES 18432              // 128*144
#define FSTAGE (2 * FK_BYTES + 2 * FV_BYTES)        // 71680
#define FLASH2_SMEM (2 * FQ_BYTES + 2 * FSTAGE)     // 212992

__device__ __forceinline__ void load_kv(
    uint32_t stg, const __nv_bfloat16* Khg, const __nv_bfloat16* Klg,
    const __nv_bfloat16* Vhg, const __nv_bfloat16* Vlg, int j0, int tid)
{
#pragma unroll
    for (int t = 0; t < 4; ++t) {
        const int c = t * 256 + tid;        // 0..1023
        const int row = c >> 4, ch = c & 15;
        const uint32_t dst = stg + row * 272 + ch * 16;
        const size_t src = (size_t)(j0 + row) * DD + ch * 8;
        cp16(dst, Khg + src);
        cp16(dst + FK_BYTES, Klg + src);
    }
#pragma unroll
    for (int t = 0; t < 4; ++t) {
        const int c = t * 256 + tid;        // 0..1023
        const int drow = c >> 3, ch = c & 7;
        const uint32_t dst = stg + 2 * FK_BYTES + drow * 144 + ch * 16;
        const size_t src = (size_t)drow * NN + j0 + ch * 8;
        cp16(dst, Vhg + src);
        cp16(dst + FV_BYTES, Vlg + src);
    }
}

__global__ void __launch_bounds__(256, 1) flash_mma()
{
    extern __shared__ char smc[];
    const uint32_t sb = smem_u32(smc);
    const int tid = threadIdx.x;
    const int lane = tid & 31;
    const int w = tid >> 5;
    const int bh = blockIdx.y;
    const int b = bh >> 4, h = bh & (HH - 1);
    const int qt = (gridDim.x - 1) - blockIdx.x;   // long tiles first
    const int i0 = qt * 128;

    const __nv_bfloat16* Qhg = g_qh + (size_t)bh * NN * DD;
    const __nv_bfloat16* Qlg = g_ql + (size_t)bh * NN * DD;
    const __nv_bfloat16* Khg = g_kh + (size_t)bh * NN * DD;
    const __nv_bfloat16* Klg = g_kl + (size_t)bh * NN * DD;
    const __nv_bfloat16* Vhg = g_vth + (size_t)bh * DD * NN;
    const __nv_bfloat16* Vlg = g_vtl + (size_t)bh * DD * NN;

    // Q tiles (hi+lo)
#pragma unroll
    for (int t = 0; t < 8; ++t) {
        const int c = t * 256 + tid;        // 0..2047
        const int row = c >> 4, ch = c & 15;
        const uint32_t dst = sb + row * 272 + ch * 16;
        const size_t src = (size_t)(i0 + row) * DD + ch * 8;
        cp16(dst, Qhg + src);
        cp16(dst + FQ_BYTES, Qlg + src);
    }
    load_kv(sb + 2 * FQ_BYTES, Khg, Klg, Vhg, Vlg, 0, tid);
    cp_commit();

    const int nj = 2 * qt + 2;
    float m_[2] = {-1e30f, -1e30f}, l_[2] = {0.0f, 0.0f};
    float O[16][4];
#pragma unroll
    for (int nt = 0; nt < 16; ++nt)
#pragma unroll
        for (int r = 0; r < 4; ++r) O[nt][r] = 0.0f;

    const int r0 = w * 16 + (lane >> 2);

    for (int jt = 0; jt < nj; ++jt) {
        const uint32_t stg = sb + 2 * FQ_BYTES + (jt & 1) * FSTAGE;
        if (jt + 1 < nj) {
            load_kv(sb + 2 * FQ_BYTES + ((jt + 1) & 1) * FSTAGE,
                    Khg, Klg, Vhg, Vlg, (jt + 1) * 64, tid);
            cp_commit();
            asm volatile("cp.async.wait_group 1;");
        } else {
            asm volatile("cp.async.wait_group 0;");
        }
        __syncthreads();

        // ---- S = Q K^T (3-term split, term-major issue) ----
        float S[8][4];
#pragma unroll
        for (int nt = 0; nt < 8; ++nt)
#pragma unroll
            for (int r = 0; r < 4; ++r) S[nt][r] = 0.0f;

        const int lrA = w * 16 + ((lane >> 3) & 1) * 8 + (lane & 7);
        const int cA16 = (lane >> 4) & 1;
        const int lrB = ((lane >> 4) & 1) * 8 + (lane & 7);
        const int cB16 = (lane >> 3) & 1;

#pragma unroll
        for (int ks = 0; ks < 8; ++ks) {
            uint32_t ah[4], al[4];
            const uint32_t qoff = lrA * 272 + ks * 32 + cA16 * 16;
            ldmx4(ah, sb + qoff);
            ldmx4(al, sb + FQ_BYTES + qoff);
            uint32_t bhf[4][4], blf[4][4];
#pragma unroll
            for (int jn2 = 0; jn2 < 4; ++jn2) {
                const uint32_t koff = (jn2 * 16 + lrB) * 272 + ks * 32 + cB16 * 16;
                ldmx4(bhf[jn2], stg + koff);
                ldmx4(blf[jn2], stg + FK_BYTES + koff);
            }
            // Term-major: 8 independent accumulator chains per term.
#pragma unroll
            for (int jn2 = 0; jn2 < 4; ++jn2) {
                mma16816(S[2 * jn2],     ah, bhf[jn2][0], bhf[jn2][1]);
                mma16816(S[2 * jn2 + 1], ah, bhf[jn2][2], bhf[jn2][3]);
            }
#pragma unroll
            for (int jn2 = 0; jn2 < 4; ++jn2) {
                mma16816(S[2 * jn2],     al, bhf[jn2][0], bhf[jn2][1]);
                mma16816(S[2 * jn2 + 1], al, bhf[jn2][2], bhf[jn2][3]);
            }
#pragma unroll
            for (int jn2 = 0; jn2 < 4; ++jn2) {
                mma16816(S[2 * jn2],     ah, blf[jn2][0], blf[jn2][1]);
                mma16816(S[2 * jn2 + 1], ah, blf[jn2][2], blf[jn2][3]);
            }
        }

        // ---- scale + causal mask ----
        const int j0 = jt * 64;
#pragma unroll
        for (int nt = 0; nt < 8; ++nt)
#pragma unroll
            for (int r = 0; r < 4; ++r) S[nt][r] *= SCALE;

        if (jt >= nj - 2) {
#pragma unroll
            for (int nt = 0; nt < 8; ++nt) {
                const int jc = j0 + nt * 8 + (lane & 3) * 2;
#pragma unroll
                for (int r = 0; r < 4; ++r) {
                    const int i = i0 + r0 + (r >> 1) * 8;
                    if (jc + (r & 1) > i) S[nt][r] = -1e30f;
                }
            }
        }

        // ---- online softmax (rows: r0, r0+8) ----
        float rm0 = -1e30f, rm1 = -1e30f;
#pragma unroll
        for (int nt = 0; nt < 8; ++nt) {
            rm0 = fmaxf(rm0, fmaxf(S[nt][0], S[nt][1]));
            rm1 = fmaxf(rm1, fmaxf(S[nt][2], S[nt][3]));
        }
        rm0 = fmaxf(rm0, __shfl_xor_sync(0xffffffffu, rm0, 1));
        rm0 = fmaxf(rm0, __shfl_xor_sync(0xffffffffu, rm0, 2));
        rm1 = fmaxf(rm1, __shfl_xor_sync(0xffffffffu, rm1, 1));
        rm1 = fmaxf(rm1, __shfl_xor_sync(0xffffffffu, rm1, 2));

        const float mn0 = fmaxf(m_[0], rm0);
        const float mn1 = fmaxf(m_[1], rm1);
        const float al0 = __expf(m_[0] - mn0);
        const float al1 = __expf(m_[1] - mn1);
        float rs0 = 0.0f, rs1 = 0.0f;
#pragma unroll
        for (int nt = 0; nt < 8; ++nt) {
            S[nt][0] = __expf(S[nt][0] - mn0);
            S[nt][1] = __expf(S[nt][1] - mn0);
            S[nt][2] = __expf(S[nt][2] - mn1);
            S[nt][3] = __expf(S[nt][3] - mn1);
            rs0 += S[nt][0] + S[nt][1];
            rs1 += S[nt][2] + S[nt][3];
        }
        rs0 += __shfl_xor_sync(0xffffffffu, rs0, 1);
        rs0 += __shfl_xor_sync(0xffffffffu, rs0, 2);
        rs1 += __shfl_xor_sync(0xffffffffu, rs1, 1);
        rs1 += __shfl_xor_sync(0xffffffffu, rs1, 2);

        l_[0] = l_[0] * al0 + rs0;
        l_[1] = l_[1] * al1 + rs1;
        m_[0] = mn0; m_[1] = mn1;

#pragma unroll
        for (int nt = 0; nt < 16; ++nt) {
            O[nt][0] *= al0; O[nt][1] *= al0;
            O[nt][2] *= al1; O[nt][3] *= al1;
        }

        // ---- O += P V  (3-term split, term-major over halves of 4 dt2) ----
#pragma unroll
        for (int kc = 0; kc < 4; ++kc) {
            float p00 = S[2 * kc][0],     p01 = S[2 * kc][1];
            float p02 = S[2 * kc][2],     p03 = S[2 * kc][3];
            float p10 = S[2 * kc + 1][0], p11 = S[2 * kc + 1][1];
            float p12 = S[2 * kc + 1][2], p13 = S[2 * kc + 1][3];
            uint32_t pah[4], pal[4];
            pah[0] = packbf(p00, p01);
            pah[1] = packbf(p02, p03);
            pah[2] = packbf(p10, p11);
            pah[3] = packbf(p12, p13);
            {
                __nv_bfloat162 t0 = *(__nv_bfloat162*)&pah[0];
                __nv_bfloat162 t1 = *(__nv_bfloat162*)&pah[1];
                __nv_bfloat162 t2 = *(__nv_bfloat162*)&pah[2];
                __nv_bfloat162 t3 = *(__nv_bfloat162*)&pah[3];
                pal[0] = packbf(p00 - __bfloat162float(t0.x), p01 - __bfloat162float(t0.y));
                pal[1] = packbf(p02 - __bfloat162float(t1.x), p03 - __bfloat162float(t1.y));
                pal[2] = packbf(p10 - __bfloat162float(t2.x), p11 - __bfloat162float(t2.y));
                pal[3] = packbf(p12 - __bfloat162float(t3.x), p13 - __bfloat162float(t3.y));
            }
#pragma unroll
            for (int half = 0; half < 2; ++half) {
                uint32_t vbh[4][4], vbl[4][4];
#pragma unroll
                for (int d = 0; d < 4; ++d) {
                    const int dt2 = half * 4 + d;
                    const uint32_t voff = 2 * FK_BYTES +
                        (dt2 * 16 + lrB) * 144 + kc * 32 + cB16 * 16;
                    ldmx4(vbh[d], stg + voff);
                    ldmx4(vbl[d], stg + FV_BYTES + voff);
                }
                // Term-major: 8 independent accumulator chains per term.
#pragma unroll
                for (int d = 0; d < 4; ++d) {
                    const int dt2 = half * 4 + d;
                    mma16816(O[2 * dt2],     pah, vbh[d][0], vbh[d][1]);
                    mma16816(O[2 * dt2 + 1], pah, vbh[d][2], vbh[d][3]);
                }
#pragma unroll
                for (int d = 0; d < 4; ++d) {
                    const int dt2 = half * 4 + d;
                    mma16816(O[2 * dt2],     pal, vbh[d][0], vbh[d][1]);
                    mma16816(O[2 * dt2 + 1], pal, vbh[d][2], vbh[d][3]);
                }
#pragma unroll
                for (int d = 0; d < 4; ++d) {
                    const int dt2 = half * 4 + d;
                    mma16816(O[2 * dt2],     pah, vbl[d][0], vbl[d][1]);
                    mma16816(O[2 * dt2 + 1], pah, vbl[d][2], vbl[d][3]);
                }
            }
        }
        __syncthreads();
    }

    // ---- epilogue: normalize, split-bf16 store to s_ah/s_al [B,N,E] ----
#pragma unroll
    for (int rh = 0; rh < 2; ++rh) {
        const int i = i0 + r0 + rh * 8;
        const float inv = 1.0f / l_[rh];
#pragma unroll
        for (int nt = 0; nt < 16; ++nt) {
            const int d = nt * 8 + (lane & 3) * 2;
            const size_t idx = ((size_t)(b * NN + i)) * EE + h * DD + d;
            const float o0 = O[nt][2 * rh] * inv;
            const float o1 = O[nt][2 * rh + 1] * inv;
            const __nv_bfloat16 h0 = __float2bfloat16(o0);
            const __nv_bfloat16 h1 = __float2bfloat16(o1);
            const float l0f = o0 - __bfloat162float(h0);
            const float l1f = o1 - __bfloat162float(h1);
            __nv_bfloat16 hp[2] = {h0, h1};
            __nv_bfloat16 lp[2] = {__float2bfloat16(l0f), __float2bfloat16(l1f)};
            *(uint32_t*)(s_ah + idx) = *(const uint32_t*)hp;
            *(uint32_t*)(s_al + idx) = *(const uint32_t*)lp;
        }
    }
}

// ---------------------------------------------------------------------------
// Launch
// ---------------------------------------------------------------------------
extern "C" void kernel_launch(void* const* d_in, const int* in_sizes, int n_in,
                              void* d_out, int out_size)
{
    const float* x    = (const float*)d_in[0];
    const float* Wq   = (const float*)d_in[1];
    const float* Wkv  = (const float*)d_in[2];
    const float* Wout = (const float*)d_in[3];
    float* out = (float*)d_out;

    void *xh, *xl, *wqh, *wql, *wkh, *wkl, *woh, *wol, *ah, *al;
    cudaGetSymbolAddress(&xh, s_xh);   cudaGetSymbolAddress(&xl, s_xl);
    cudaGetSymbolAddress(&wqh, s_wqh); cudaGetSymbolAddress(&wql, s_wql);
    cudaGetSymbolAddress(&wkh, s_wkh); cudaGetSymbolAddress(&wkl, s_wkl);
    cudaGetSymbolAddress(&woh, s_woh); cudaGetSymbolAddress(&wol, s_wol);
    cudaGetSymbolAddress(&ah, s_ah);   cudaGetSymbolAddress(&al, s_al);

    split_kernel<<<8192, 256>>>(x,    (__nv_bfloat16*)xh,  (__nv_bfloat16*)xl,  2097152);
    split_kernel<<<4096, 256>>>(Wq,   (__nv_bfloat16*)wqh, (__nv_bfloat16*)wql, 1048576);
    split_kernel<<<8192, 256>>>(Wkv,  (__nv_bfloat16*)wkh, (__nv_bfloat16*)wkl, 2097152);
    split_kernel<<<4096, 256>>>(Wout, (__nv_bfloat16*)woh, (__nv_bfloat16*)wol, 1048576);

    cudaFuncSetAttribute(gemm_mma<0>, cudaFuncAttributeMaxDynamicSharedMemorySize, GEMM_SMEM);
    cudaFuncSetAttribute(gemm_mma<1>, cudaFuncAttributeMaxDynamicSharedMemorySize, GEMM_SMEM);
    cudaFuncSetAttribute(gemm_mma<2>, cudaFuncAttributeMaxDynamicSharedMemorySize, GEMM_SMEM);

    gemm_mma<1><<<dim3(EE / 128, MTOT / 128), 256, GEMM_SMEM>>>(
        (const __nv_bfloat16*)xh, (const __nv_bfloat16*)xl,
        (const __nv_bfloat16*)wqh, (const __nv_bfloat16*)wql, nullptr, EE);
    gemm_mma<2><<<dim3(2 * EE / 128, MTOT / 128), 256, GEMM_SMEM>>>(
        (const __nv_bfloat16*)xh, (const __nv_bfloat16*)xl,
        (const __nv_bfloat16*)wkh, (const __nv_bfloat16*)wkl, nullptr, EE);

    cudaFuncSetAttribute(flash_mma, cudaFuncAttributeMaxDynamicSharedMemorySize,
                         FLASH2_SMEM);
    flash_mma<<<dim3(NN / 128, BB * HH), 256, FLASH2_SMEM>>>();

    gemm_mma<0><<<dim3(EE / 128, MTOT / 128), 256, GEMM_SMEM>>>(
        (const __nv_bfloat16*)ah, (const __nv_bfloat16*)al,
        (const __nv_bfloat16*)woh, (const __nv_bfloat16*)wol, out, EE);
}

// round 12
// speedup vs baseline: 1.1287x; 1.1287x over previous
#include <cuda_runtime.h>
#include <cuda_bf16.h>
#include <cstdint>

// Problem constants
#define BB 2
#define NN 2048
#define EE 2048
#define HH 16
#define DD 128
#define MTOT (BB * NN)
#define SCALE 0.08838834764831843f

// ---------------------------------------------------------------------------
// Device scratch (allocation-free rule)
// ---------------------------------------------------------------------------
__device__ __nv_bfloat16 g_qh[(size_t)BB * HH * NN * DD];  // Q hi [B,H,N,D]
__device__ __nv_bfloat16 g_ql[(size_t)BB * HH * NN * DD];  // Q lo
__device__ __nv_bfloat16 g_kh[(size_t)BB * HH * NN * DD];  // K hi [B,H,N,D]
__device__ __nv_bfloat16 g_kl[(size_t)BB * HH * NN * DD];  // K lo
__device__ __nv_bfloat16 g_vth[(size_t)BB * HH * DD * NN]; // V hi [B,H,D,N]
__device__ __nv_bfloat16 g_vtl[(size_t)BB * HH * DD * NN]; // V lo [B,H,D,N]

__device__ __nv_bfloat16 s_xh[8388608],  s_xl[8388608];   // x split     [M,K]
__device__ __nv_bfloat16 s_wqh[4194304], s_wql[4194304];  // Wq split    [E,K]
__device__ __nv_bfloat16 s_wkh[8388608], s_wkl[8388608];  // Wkv split   [2E,K]
__device__ __nv_bfloat16 s_woh[4194304], s_wol[4194304];  // Wout split  [E,K]
__device__ __nv_bfloat16 s_ah[8388608],  s_al[8388608];   // attn out split [B,N,E]

// ---------------------------------------------------------------------------
// Helpers
// ---------------------------------------------------------------------------
__device__ __forceinline__ uint32_t smem_u32(const void* p) {
    uint32_t a;
    asm("{ .reg .u64 t; cvta.to.shared.u64 t, %1; cvt.u32.u64 %0, t; }"
        : "=r"(a) : "l"(p));
    return a;
}
__device__ __forceinline__ void cp16(uint32_t dst, const void* src) {
    asm volatile("cp.async.cg.shared.global [%0], [%1], 16;"
                 :: "r"(dst), "l"(src));
}
__device__ __forceinline__ void cp_commit() {
    asm volatile("cp.async.commit_group;");
}
__device__ __forceinline__ uint32_t swz(uint32_t off) {   // SW64 for 64B rows
    return off ^ ((off >> 3) & 0x30);
}
__device__ __forceinline__ void ldmx4(uint32_t* f, uint32_t addr) {
    asm volatile("ldmatrix.sync.aligned.m8n8.x4.shared.b16 {%0,%1,%2,%3}, [%4];"
                 : "=r"(f[0]), "=r"(f[1]), "=r"(f[2]), "=r"(f[3]) : "r"(addr));
}
__device__ __forceinline__ void mma16816(float* c, const uint32_t* a,
                                         uint32_t b0, uint32_t b1) {
    asm volatile(
        "mma.sync.aligned.m16n8k16.row.col.f32.bf16.bf16.f32 "
        "{%0,%1,%2,%3}, {%4,%5,%6,%7}, {%8,%9}, {%0,%1,%2,%3};"
        : "+f"(c[0]), "+f"(c[1]), "+f"(c[2]), "+f"(c[3])
        : "r"(a[0]), "r"(a[1]), "r"(a[2]), "r"(a[3]), "r"(b0), "r"(b1));
}
__device__ __forceinline__ uint32_t packbf(float a, float b) {
    __nv_bfloat162 t = __floats2bfloat162_rn(a, b);
    return *(uint32_t*)&t;
}

// ---------------------------------------------------------------------------
// Merged split kernel: all four fp32 inputs -> (hi, lo) bf16 in one launch
// ---------------------------------------------------------------------------
#define N4_X  2097152
#define N4_WQ 1048576
#define N4_WK 2097152
#define N4_WO 1048576
#define N4_TOT (N4_X + N4_WQ + N4_WK + N4_WO)   // 6291456

__global__ __launch_bounds__(256) void split_all_kernel(
    const float* __restrict__ x, const float* __restrict__ wq,
    const float* __restrict__ wk, const float* __restrict__ wo)
{
    int i = blockIdx.x * blockDim.x + threadIdx.x;
    if (i >= N4_TOT) return;
    const float* src;
    __nv_bfloat16 *hi, *lo;
    int off;
    if (i < N4_X) {
        src = x; hi = s_xh; lo = s_xl; off = i;
    } else if (i < N4_X + N4_WQ) {
        src = wq; hi = s_wqh; lo = s_wql; off = i - N4_X;
    } else if (i < N4_X + N4_WQ + N4_WK) {
        src = wk; hi = s_wkh; lo = s_wkl; off = i - N4_X - N4_WQ;
    } else {
        src = wo; hi = s_woh; lo = s_wol; off = i - N4_X - N4_WQ - N4_WK;
    }
    float4 v = ((const float4*)src)[off];
    float vv[4] = {v.x, v.y, v.z, v.w};
    __nv_bfloat16 h[4], l[4];
#pragma unroll
    for (int j = 0; j < 4; ++j) {
        h[j] = __float2bfloat16(vv[j]);
        l[j] = __float2bfloat16(vv[j] - __bfloat162float(h[j]));
    }
    ((uint2*)hi)[off] = *(const uint2*)h;
    ((uint2*)lo)[off] = *(const uint2*)l;
}

// ---------------------------------------------------------------------------
// bf16-split GEMM via mma.sync, 3-stage cp.async pipeline.
// Interleaved (per-accumulator) 3-term order — the proven-fast schedule.
// MODE 0: Cout fp32 [M,E]  (Wout projection)
// MODE 3: merged QKV: blockIdx.x selects Q / K / V target + weight matrix
// ---------------------------------------------------------------------------
#define TILE_BYTES 8192
#define STAGE_BYTES (4 * TILE_BYTES)
#define GEMM_SMEM 98304            // 3 stages x 32KB; epilogue 67584 reuses it

__device__ __forceinline__ void load_chunk(
    uint32_t stage, const __nv_bfloat16* Ahp, const __nv_bfloat16* Alp,
    const __nv_bfloat16* Whp, const __nv_bfloat16* Wlp,
    int m0, int wrow0, int k0, int tid)
{
#pragma unroll
    for (int t = 0; t < 2; ++t) {
        const int c = tid + t * 256;
        const int row = c >> 2;
        const int kc = c & 3;
        const uint32_t so = swz((uint32_t)(row * 64 + kc * 16));
        const size_t gA = (size_t)(m0 + row) * EE + k0 + kc * 8;
        const size_t gW = (size_t)(wrow0 + row) * EE + k0 + kc * 8;
        cp16(stage + 0 * TILE_BYTES + so, Ahp + gA);
        cp16(stage + 1 * TILE_BYTES + so, Alp + gA);
        cp16(stage + 2 * TILE_BYTES + so, Whp + gW);
        cp16(stage + 3 * TILE_BYTES + so, Wlp + gW);
    }
}

template <int MODE>
__global__ void __launch_bounds__(256) gemm_mma(
    const __nv_bfloat16* __restrict__ Ahp, const __nv_bfloat16* __restrict__ Alp,
    const __nv_bfloat16* __restrict__ Wqhp, const __nv_bfloat16* __restrict__ Wqlp,
    const __nv_bfloat16* __restrict__ Wkhp, const __nv_bfloat16* __restrict__ Wklp,
    float* __restrict__ Cout)
{
    extern __shared__ char smem[];
    const uint32_t sb = smem_u32(smem);
    const int tid = threadIdx.x;
    const int lane = tid & 31;
    const int w = tid >> 5;
    const int wm = w >> 2;
    const int wn = w & 3;
    const int m0 = blockIdx.y * 128;
    const int n0 = blockIdx.x * 128;

    // Select weight matrix + epilogue kind
    // MODE 0: ek=3 (Cout). MODE 3: n0<E -> Q (ek 0); else Wkv: K (ek 1) / V (ek 2)
    const __nv_bfloat16 *Whp, *Wlp;
    int wrow0, ek;
    if (MODE == 0) {
        Whp = Wqhp; Wlp = Wqlp; wrow0 = n0; ek = 3;
    } else {
        if (n0 < EE) { Whp = Wqhp; Wlp = Wqlp; wrow0 = n0; ek = 0; }
        else {
            Whp = Wkhp; Wlp = Wklp; wrow0 = n0 - EE;
            ek = (wrow0 < EE) ? 1 : 2;
        }
    }

    float acc[4][4][4];
#pragma unroll
    for (int i = 0; i < 4; ++i)
#pragma unroll
        for (int j = 0; j < 4; ++j)
#pragma unroll
            for (int r = 0; r < 4; ++r) acc[i][j][r] = 0.0f;

    const int sel = lane >> 3;
    const int lrow8 = ((sel & 1) << 3) + (lane & 7);
    const int lkc = sel >> 1;

    const int nk = EE >> 5;     // 64
    load_chunk(sb + 0 * STAGE_BYTES, Ahp, Alp, Whp, Wlp, m0, wrow0, 0, tid);
    cp_commit();
    load_chunk(sb + 1 * STAGE_BYTES, Ahp, Alp, Whp, Wlp, m0, wrow0, 32, tid);
    cp_commit();

    int stg_idx = 0;
    for (int kt = 0; kt < nk; ++kt) {
        const uint32_t stage = sb + stg_idx * STAGE_BYTES;

        if (kt + 2 < nk) {
            int nidx = stg_idx + 2; if (nidx >= 3) nidx -= 3;
            load_chunk(sb + nidx * STAGE_BYTES, Ahp, Alp, Whp, Wlp,
                       m0, wrow0, (kt + 2) << 5, tid);
            cp_commit();
            asm volatile("cp.async.wait_group 2;");
        } else if (kt + 1 < nk) {
            asm volatile("cp.async.wait_group 1;");
        } else {
            asm volatile("cp.async.wait_group 0;");
        }
        __syncthreads();

#pragma unroll
        for (int kk = 0; kk < 2; ++kk) {
            const int kchunk = kk * 2 + lkc;
            uint32_t ah[4][4], al[4][4];
#pragma unroll
            for (int i = 0; i < 4; ++i) {
                const int r = wm * 64 + i * 16 + lrow8;
                const uint32_t off = swz((uint32_t)(r * 64 + kchunk * 16));
                ldmx4(ah[i], stage + 0 * TILE_BYTES + off);
                ldmx4(al[i], stage + 1 * TILE_BYTES + off);
            }
            uint32_t bh[2][4], bl[2][4];
#pragma unroll
            for (int j2 = 0; j2 < 2; ++j2) {
                const int r = wn * 32 + j2 * 16 + lrow8;
                const uint32_t off = swz((uint32_t)(r * 64 + kchunk * 16));
                ldmx4(bh[j2], stage + 2 * TILE_BYTES + off);
                ldmx4(bl[j2], stage + 3 * TILE_BYTES + off);
            }
            // Proven-fast interleaved order (ptxas schedules well).
#pragma unroll
            for (int i = 0; i < 4; ++i) {
#pragma unroll
                for (int j = 0; j < 4; ++j) {
                    const int j2 = j >> 1, jo = j & 1;
                    mma16816(acc[i][j], ah[i], bh[j2][jo], bh[j2][2 + jo]);
                    mma16816(acc[i][j], al[i], bh[j2][jo], bh[j2][2 + jo]);
                    mma16816(acc[i][j], ah[i], bl[j2][jo], bl[j2][2 + jo]);
                }
            }
        }
        __syncthreads();
        ++stg_idx; if (stg_idx >= 3) stg_idx = 0;
    }

    // ---- Epilogue ----
    float* Ss = (float*)smem;   // [128][132]
#pragma unroll
    for (int i = 0; i < 4; ++i) {
        const int r = wm * 64 + i * 16 + (lane >> 2);
#pragma unroll
        for (int j = 0; j < 4; ++j) {
            const int cc = wn * 32 + j * 8 + 2 * (lane & 3);
            Ss[r * 132 + cc]           = acc[i][j][0];
            Ss[r * 132 + cc + 1]       = acc[i][j][1];
            Ss[(r + 8) * 132 + cc]     = acc[i][j][2];
            Ss[(r + 8) * 132 + cc + 1] = acc[i][j][3];
        }
    }
    __syncthreads();

    const int b = m0 >> 11;
    const int nbase = m0 & (NN - 1);

    if (ek == 3) {
#pragma unroll
        for (int it = 0; it < 16; ++it) {
            const int f = it * 256 + tid;
            const int r = f >> 5;
            const int c4 = (f & 31) << 2;
            float4 v = *(const float4*)(Ss + r * 132 + c4);
            *(float4*)(Cout + (size_t)(m0 + r) * EE + n0 + c4) = v;
        }
    } else if (ek == 0 || ek == 1) {
        const int h = (wrow0 & (EE - 1)) >> 7;
        __nv_bfloat16* dh = (ek == 0 ? g_qh : g_kh) +
            ((size_t)(b * HH + h) * NN + nbase) * DD;
        __nv_bfloat16* dl = (ek == 0 ? g_ql : g_kl) +
            ((size_t)(b * HH + h) * NN + nbase) * DD;
#pragma unroll
        for (int it = 0; it < 16; ++it) {
            const int f = it * 256 + tid;
            const int r = f >> 5;
            const int c4 = (f & 31) << 2;
            float4 v = *(const float4*)(Ss + r * 132 + c4);
            float vv[4] = {v.x, v.y, v.z, v.w};
            __nv_bfloat16 hi[4], lo[4];
#pragma unroll
            for (int q = 0; q < 4; ++q) {
                hi[q] = __float2bfloat16(vv[q]);
                lo[q] = __float2bfloat16(vv[q] - __bfloat162float(hi[q]));
            }
            *(uint2*)(dh + (size_t)r * DD + c4) = *(const uint2*)hi;
            *(uint2*)(dl + (size_t)r * DD + c4) = *(const uint2*)lo;
        }
    } else {
        // V -> g_vth/g_vtl bf16 split, transposed [B,H,D,N]
        const int h2 = (wrow0 - EE) >> 7;
        const int col = tid >> 1;
        const int rh2 = tid & 1;
        const size_t dof = ((size_t)(b * HH + h2) * DD + col) * NN +
                           nbase + (rh2 << 6);
        __nv_bfloat16* dsth = g_vth + dof;
        __nv_bfloat16* dstl = g_vtl + dof;
#pragma unroll
        for (int i = 0; i < 16; ++i) {
            const int r = (rh2 << 6) + (i << 2);
            __nv_bfloat16 vh4[4], vl4[4];
#pragma unroll
            for (int q = 0; q < 4; ++q) {
                const float f = Ss[(r + q) * 132 + col];
                vh4[q] = __float2bfloat16(f);
                vl4[q] = __float2bfloat16(f - __bfloat162float(vh4[q]));
            }
            *(uint2*)(dsth + (i << 2)) = *(const uint2*)vh4;
            *(uint2*)(dstl + (i << 2)) = *(const uint2*)vl4;
        }
    }
}

// ---------------------------------------------------------------------------
// Flash attention v2 (R10 exact — the 1693.7us schedule):
// mma.sync, 3-term splits for QK^T AND PV.
// Br=128 (8 warps x 16 rows), Bc=64, D=128.
// ---------------------------------------------------------------------------
#define FQ_BYTES 34816              // 128*272
#define FK_BYTES 17408              // 64*272
#define FV_BYTES 18432              // 128*144
#define FSTAGE (2 * FK_BYTES + 2 * FV_BYTES)        // 71680
#define FLASH2_SMEM (2 * FQ_BYTES + 2 * FSTAGE)     // 212992

__device__ __forceinline__ void load_kv(
    uint32_t stg, const __nv_bfloat16* Khg, const __nv_bfloat16* Klg,
    const __nv_bfloat16* Vhg, const __nv_bfloat16* Vlg, int j0, int tid)
{
#pragma unroll
    for (int t = 0; t < 4; ++t) {
        const int c = t * 256 + tid;        // 0..1023
        const int row = c >> 4, ch = c & 15;
        const uint32_t dst = stg + row * 272 + ch * 16;
        const size_t src = (size_t)(j0 + row) * DD + ch * 8;
        cp16(dst, Khg + src);
        cp16(dst + FK_BYTES, Klg + src);
    }
#pragma unroll
    for (int t = 0; t < 4; ++t) {
        const int c = t * 256 + tid;        // 0..1023
        const int drow = c >> 3, ch = c & 7;
        const uint32_t dst = stg + 2 * FK_BYTES + drow * 144 + ch * 16;
        const size_t src = (size_t)drow * NN + j0 + ch * 8;
        cp16(dst, Vhg + src);
        cp16(dst + FV_BYTES, Vlg + src);
    }
}

__global__ void __launch_bounds__(256, 1) flash_mma()
{
    extern __shared__ char smc[];
    const uint32_t sb = smem_u32(smc);
    const int tid = threadIdx.x;
    const int lane = tid & 31;
    const int w = tid >> 5;
    const int bh = blockIdx.y;
    const int b = bh >> 4, h = bh & (HH - 1);
    const int qt = (gridDim.x - 1) - blockIdx.x;   // long tiles first
    const int i0 = qt * 128;

    const __nv_bfloat16* Qhg = g_qh + (size_t)bh * NN * DD;
    const __nv_bfloat16* Qlg = g_ql + (size_t)bh * NN * DD;
    const __nv_bfloat16* Khg = g_kh + (size_t)bh * NN * DD;
    const __nv_bfloat16* Klg = g_kl + (size_t)bh * NN * DD;
    const __nv_bfloat16* Vhg = g_vth + (size_t)bh * DD * NN;
    const __nv_bfloat16* Vlg = g_vtl + (size_t)bh * DD * NN;

    // Q tiles (hi+lo)
#pragma unroll
    for (int t = 0; t < 8; ++t) {
        const int c = t * 256 + tid;        // 0..2047
        const int row = c >> 4, ch = c & 15;
        const uint32_t dst = sb + row * 272 + ch * 16;
        const size_t src = (size_t)(i0 + row) * DD + ch * 8;
        cp16(dst, Qhg + src);
        cp16(dst + FQ_BYTES, Qlg + src);
    }
    load_kv(sb + 2 * FQ_BYTES, Khg, Klg, Vhg, Vlg, 0, tid);
    cp_commit();

    const int nj = 2 * qt + 2;
    float m_[2] = {-1e30f, -1e30f}, l_[2] = {0.0f, 0.0f};
    float O[16][4];
#pragma unroll
    for (int nt = 0; nt < 16; ++nt)
#pragma unroll
        for (int r = 0; r < 4; ++r) O[nt][r] = 0.0f;

    const int r0 = w * 16 + (lane >> 2);

    for (int jt = 0; jt < nj; ++jt) {
        const uint32_t stg = sb + 2 * FQ_BYTES + (jt & 1) * FSTAGE;
        if (jt + 1 < nj) {
            load_kv(sb + 2 * FQ_BYTES + ((jt + 1) & 1) * FSTAGE,
                    Khg, Klg, Vhg, Vlg, (jt + 1) * 64, tid);
            cp_commit();
            asm volatile("cp.async.wait_group 1;");
        } else {
            asm volatile("cp.async.wait_group 0;");
        }
        __syncthreads();

        // ---- S = Q K^T (3-term split) ----
        float S[8][4];
#pragma unroll
        for (int nt = 0; nt < 8; ++nt)
#pragma unroll
            for (int r = 0; r < 4; ++r) S[nt][r] = 0.0f;

        const int lrA = w * 16 + ((lane >> 3) & 1) * 8 + (lane & 7);
        const int cA16 = (lane >> 4) & 1;
        const int lrB = ((lane >> 4) & 1) * 8 + (lane & 7);
        const int cB16 = (lane >> 3) & 1;

#pragma unroll
        for (int ks = 0; ks < 8; ++ks) {
            uint32_t ah[4], al[4];
            const uint32_t qoff = lrA * 272 + ks * 32 + cA16 * 16;
            ldmx4(ah, sb + qoff);
            ldmx4(al, sb + FQ_BYTES + qoff);
#pragma unroll
            for (int jn2 = 0; jn2 < 4; ++jn2) {
                uint32_t bhf[4], blf[4];
                const uint32_t koff = (jn2 * 16 + lrB) * 272 + ks * 32 + cB16 * 16;
                ldmx4(bhf, stg + koff);
                ldmx4(blf, stg + FK_BYTES + koff);
                mma16816(S[2 * jn2],     ah, bhf[0], bhf[1]);
                mma16816(S[2 * jn2],     al, bhf[0], bhf[1]);
                mma16816(S[2 * jn2],     ah, blf[0], blf[1]);
                mma16816(S[2 * jn2 + 1], ah, bhf[2], bhf[3]);
                mma16816(S[2 * jn2 + 1], al, bhf[2], bhf[3]);
                mma16816(S[2 * jn2 + 1], ah, blf[2], blf[3]);
            }
        }

        // ---- scale + causal mask ----
        const int j0 = jt * 64;
#pragma unroll
        for (int nt = 0; nt < 8; ++nt)
#pragma unroll
            for (int r = 0; r < 4; ++r) S[nt][r] *= SCALE;

        if (jt >= nj - 2) {
#pragma unroll
            for (int nt = 0; nt < 8; ++nt) {
                const int jc = j0 + nt * 8 + (lane & 3) * 2;
#pragma unroll
                for (int r = 0; r < 4; ++r) {
                    const int i = i0 + r0 + (r >> 1) * 8;
                    if (jc + (r & 1) > i) S[nt][r] = -1e30f;
                }
            }
        }

        // ---- online softmax (rows: r0, r0+8) ----
        float rm0 = -1e30f, rm1 = -1e30f;
#pragma unroll
        for (int nt = 0; nt < 8; ++nt) {
            rm0 = fmaxf(rm0, fmaxf(S[nt][0], S[nt][1]));
            rm1 = fmaxf(rm1, fmaxf(S[nt][2], S[nt][3]));
        }
        rm0 = fmaxf(rm0, __shfl_xor_sync(0xffffffffu, rm0, 1));
        rm0 = fmaxf(rm0, __shfl_xor_sync(0xffffffffu, rm0, 2));
        rm1 = fmaxf(rm1, __shfl_xor_sync(0xffffffffu, rm1, 1));
        rm1 = fmaxf(rm1, __shfl_xor_sync(0xffffffffu, rm1, 2));

        const float mn0 = fmaxf(m_[0], rm0);
        const float mn1 = fmaxf(m_[1], rm1);
        const float al0 = __expf(m_[0] - mn0);
        const float al1 = __expf(m_[1] - mn1);
        float rs0 = 0.0f, rs1 = 0.0f;
#pragma unroll
        for (int nt = 0; nt < 8; ++nt) {
            S[nt][0] = __expf(S[nt][0] - mn0);
            S[nt][1] = __expf(S[nt][1] - mn0);
            S[nt][2] = __expf(S[nt][2] - mn1);
            S[nt][3] = __expf(S[nt][3] - mn1);
            rs0 += S[nt][0] + S[nt][1];
            rs1 += S[nt][2] + S[nt][3];
        }
        rs0 += __shfl_xor_sync(0xffffffffu, rs0, 1);
        rs0 += __shfl_xor_sync(0xffffffffu, rs0, 2);
        rs1 += __shfl_xor_sync(0xffffffffu, rs1, 1);
        rs1 += __shfl_xor_sync(0xffffffffu, rs1, 2);

        l_[0] = l_[0] * al0 + rs0;
        l_[1] = l_[1] * al1 + rs1;
        m_[0] = mn0; m_[1] = mn1;

#pragma unroll
        for (int nt = 0; nt < 16; ++nt) {
            O[nt][0] *= al0; O[nt][1] *= al0;
            O[nt][2] *= al1; O[nt][3] *= al1;
        }

        // ---- O += P V  (3-term split: Ph*Vh + Pl*Vh + Ph*Vl) ----
#pragma unroll
        for (int kc = 0; kc < 4; ++kc) {
            float p00 = S[2 * kc][0],     p01 = S[2 * kc][1];
            float p02 = S[2 * kc][2],     p03 = S[2 * kc][3];
            float p10 = S[2 * kc + 1][0], p11 = S[2 * kc + 1][1];
            float p12 = S[2 * kc + 1][2], p13 = S[2 * kc + 1][3];
            uint32_t pah[4], pal[4];
            pah[0] = packbf(p00, p01);
            pah[1] = packbf(p02, p03);
            pah[2] = packbf(p10, p11);
            pah[3] = packbf(p12, p13);
            {
                __nv_bfloat162 t0 = *(__nv_bfloat162*)&pah[0];
                __nv_bfloat162 t1 = *(__nv_bfloat162*)&pah[1];
                __nv_bfloat162 t2 = *(__nv_bfloat162*)&pah[2];
                __nv_bfloat162 t3 = *(__nv_bfloat162*)&pah[3];
                pal[0] = packbf(p00 - __bfloat162float(t0.x), p01 - __bfloat162float(t0.y));
                pal[1] = packbf(p02 - __bfloat162float(t1.x), p03 - __bfloat162float(t1.y));
                pal[2] = packbf(p10 - __bfloat162float(t2.x), p11 - __bfloat162float(t2.y));
                pal[3] = packbf(p12 - __bfloat162float(t3.x), p13 - __bfloat162float(t3.y));
            }
#pragma unroll
            for (int dt2 = 0; dt2 < 8; ++dt2) {
                uint32_t vbh[4], vbl[4];
                const uint32_t voff = 2 * FK_BYTES +
                    (dt2 * 16 + lrB) * 144 + kc * 32 + cB16 * 16;
                ldmx4(vbh, stg + voff);
                ldmx4(vbl, stg + FV_BYTES + voff);
                mma16816(O[2 * dt2],     pah, vbh[0], vbh[1]);
                mma16816(O[2 * dt2],     pal, vbh[0], vbh[1]);
                mma16816(O[2 * dt2],     pah, vbl[0], vbl[1]);
                mma16816(O[2 * dt2 + 1], pah, vbh[2], vbh[3]);
                mma16816(O[2 * dt2 + 1], pal, vbh[2], vbh[3]);
                mma16816(O[2 * dt2 + 1], pah, vbl[2], vbl[3]);
            }
        }
        __syncthreads();
    }

    // ---- epilogue: normalize, split-bf16 store to s_ah/s_al [B,N,E] ----
#pragma unroll
    for (int rh = 0; rh < 2; ++rh) {
        const int i = i0 + r0 + rh * 8;
        const float inv = 1.0f / l_[rh];
#pragma unroll
        for (int nt = 0; nt < 16; ++nt) {
            const int d = nt * 8 + (lane & 3) * 2;
            const size_t idx = ((size_t)(b * NN + i)) * EE + h * DD + d;
            const float o0 = O[nt][2 * rh] * inv;
            const float o1 = O[nt][2 * rh + 1] * inv;
            const __nv_bfloat16 h0 = __float2bfloat16(o0);
            const __nv_bfloat16 h1 = __float2bfloat16(o1);
            const float l0f = o0 - __bfloat162float(h0);
            const float l1f = o1 - __bfloat162float(h1);
            __nv_bfloat16 hp[2] = {h0, h1};
            __nv_bfloat16 lp[2] = {__float2bfloat16(l0f), __float2bfloat16(l1f)};
            *(uint32_t*)(s_ah + idx) = *(const uint32_t*)hp;
            *(uint32_t*)(s_al + idx) = *(const uint32_t*)lp;
        }
    }
}

// ---------------------------------------------------------------------------
// Launch
// ---------------------------------------------------------------------------
extern "C" void kernel_launch(void* const* d_in, const int* in_sizes, int n_in,
                              void* d_out, int out_size)
{
    const float* x    = (const float*)d_in[0];
    const float* Wq   = (const float*)d_in[1];
    const float* Wkv  = (const float*)d_in[2];
    const float* Wout = (const float*)d_in[3];
    float* out = (float*)d_out;

    void *xh, *xl, *wqh, *wql, *wkh, *wkl, *woh, *wol, *ah, *al;
    cudaGetSymbolAddress(&xh, s_xh);   cudaGetSymbolAddress(&xl, s_xl);
    cudaGetSymbolAddress(&wqh, s_wqh); cudaGetSymbolAddress(&wql, s_wql);
    cudaGetSymbolAddress(&wkh, s_wkh); cudaGetSymbolAddress(&wkl, s_wkl);
    cudaGetSymbolAddress(&woh, s_woh); cudaGetSymbolAddress(&wol, s_wol);
    cudaGetSymbolAddress(&ah, s_ah);   cudaGetSymbolAddress(&al, s_al);

    // One merged split launch for all four inputs
    split_all_kernel<<<(N4_TOT + 255) / 256, 256>>>(x, Wq, Wkv, Wout);

    cudaFuncSetAttribute(gemm_mma<0>, cudaFuncAttributeMaxDynamicSharedMemorySize, GEMM_SMEM);
    cudaFuncSetAttribute(gemm_mma<3>, cudaFuncAttributeMaxDynamicSharedMemorySize, GEMM_SMEM);

    // Merged QKV projection: grid.x covers [Q | K | V] column tiles
    gemm_mma<3><<<dim3(3 * EE / 128, MTOT / 128), 256, GEMM_SMEM>>>(
        (const __nv_bfloat16*)xh, (const __nv_bfloat16*)xl,
        (const __nv_bfloat16*)wqh, (const __nv_bfloat16*)wql,
        (const __nv_bfloat16*)wkh, (const __nv_bfloat16*)wkl, nullptr);

    cudaFuncSetAttribute(flash_mma, cudaFuncAttributeMaxDynamicSharedMemorySize,
                         FLASH2_SMEM);
    flash_mma<<<dim3(NN / 128, BB * HH), 256, FLASH2_SMEM>>>();

    // Output projection
    gemm_mma<0><<<dim3(EE / 128, MTOT / 128), 256, GEMM_SMEM>>>(
        (const __nv_bfloat16*)ah, (const __nv_bfloat16*)al,
        (const __nv_bfloat16*)woh, (const __nv_bfloat16*)wol,
        nullptr, nullptr, out);
}

// round 13
// speedup vs baseline: 2.1322x; 1.8891x over previous
#include <cuda_runtime.h>
#include <cuda_bf16.h>
#include <cuda_fp16.h>
#include <cstdint>

// Problem constants
#define BB 2
#define NN 2048
#define EE 2048
#define HH 16
#define DD 128
#define MTOT (BB * NN)
#define SCALE 0.08838834764831843f

// ---------------------------------------------------------------------------
// Device scratch (allocation-free rule)
// ---------------------------------------------------------------------------
__device__ __nv_bfloat16 g_qh[(size_t)BB * HH * NN * DD];  // Q hi [B,H,N,D]
__device__ __nv_bfloat16 g_ql[(size_t)BB * HH * NN * DD];  // Q lo
__device__ __nv_bfloat16 g_kh[(size_t)BB * HH * NN * DD];  // K hi [B,H,N,D]
__device__ __nv_bfloat16 g_kl[(size_t)BB * HH * NN * DD];  // K lo
__device__ __nv_bfloat16 g_vth[(size_t)BB * HH * DD * NN]; // V hi [B,H,D,N]
__device__ __nv_bfloat16 g_vtl[(size_t)BB * HH * DD * NN]; // V lo [B,H,D,N]

__device__ __half s_xf[8388608];    // x    fp16 [M,K]
__device__ __half s_wqf[4194304];   // Wq   fp16 [E,K]
__device__ __half s_wkf[8388608];   // Wkv  fp16 [2E,K]
__device__ __half s_wof[4194304];   // Wout fp16 [E,K]
__device__ __half s_af[8388608];    // attn fp16 [B,N,E]

// ---------------------------------------------------------------------------
// Helpers
// ---------------------------------------------------------------------------
__device__ __forceinline__ uint32_t smem_u32(const void* p) {
    uint32_t a;
    asm("{ .reg .u64 t; cvta.to.shared.u64 t, %1; cvt.u32.u64 %0, t; }"
        : "=r"(a) : "l"(p));
    return a;
}
__device__ __forceinline__ void cp16(uint32_t dst, const void* src) {
    asm volatile("cp.async.cg.shared.global [%0], [%1], 16;"
                 :: "r"(dst), "l"(src));
}
__device__ __forceinline__ void cp_commit() {
    asm volatile("cp.async.commit_group;");
}
__device__ __forceinline__ uint32_t swz(uint32_t off) {   // SW64 for 64B rows
    return off ^ ((off >> 3) & 0x30);
}
__device__ __forceinline__ void ldmx4(uint32_t* f, uint32_t addr) {
    asm volatile("ldmatrix.sync.aligned.m8n8.x4.shared.b16 {%0,%1,%2,%3}, [%4];"
                 : "=r"(f[0]), "=r"(f[1]), "=r"(f[2]), "=r"(f[3]) : "r"(addr));
}
// bf16 MMA (flash)
__device__ __forceinline__ void mma16816(float* c, const uint32_t* a,
                                         uint32_t b0, uint32_t b1) {
    asm volatile(
        "mma.sync.aligned.m16n8k16.row.col.f32.bf16.bf16.f32 "
        "{%0,%1,%2,%3}, {%4,%5,%6,%7}, {%8,%9}, {%0,%1,%2,%3};"
        : "+f"(c[0]), "+f"(c[1]), "+f"(c[2]), "+f"(c[3])
        : "r"(a[0]), "r"(a[1]), "r"(a[2]), "r"(a[3]), "r"(b0), "r"(b1));
}
// fp16 MMA (projections)
__device__ __forceinline__ void mma16816h(float* c, const uint32_t* a,
                                          uint32_t b0, uint32_t b1) {
    asm volatile(
        "mma.sync.aligned.m16n8k16.row.col.f32.f16.f16.f32 "
        "{%0,%1,%2,%3}, {%4,%5,%6,%7}, {%8,%9}, {%0,%1,%2,%3};"
        : "+f"(c[0]), "+f"(c[1]), "+f"(c[2]), "+f"(c[3])
        : "r"(a[0]), "r"(a[1]), "r"(a[2]), "r"(a[3]), "r"(b0), "r"(b1));
}
__device__ __forceinline__ uint32_t packbf(float a, float b) {
    __nv_bfloat162 t = __floats2bfloat162_rn(a, b);
    return *(uint32_t*)&t;
}

// ---------------------------------------------------------------------------
// Merged convert kernel: all four fp32 inputs -> fp16 in one launch
// ---------------------------------------------------------------------------
#define N4_X  2097152
#define N4_WQ 1048576
#define N4_WK 2097152
#define N4_WO 1048576
#define N4_TOT (N4_X + N4_WQ + N4_WK + N4_WO)   // 6291456

__global__ __launch_bounds__(256) void split_all_kernel(
    const float* __restrict__ x, const float* __restrict__ wq,
    const float* __restrict__ wk, const float* __restrict__ wo)
{
    int i = blockIdx.x * blockDim.x + threadIdx.x;
    if (i >= N4_TOT) return;
    const float* src;
    __half* dst;
    int off;
    if (i < N4_X) {
        src = x; dst = s_xf; off = i;
    } else if (i < N4_X + N4_WQ) {
        src = wq; dst = s_wqf; off = i - N4_X;
    } else if (i < N4_X + N4_WQ + N4_WK) {
        src = wk; dst = s_wkf; off = i - N4_X - N4_WQ;
    } else {
        src = wo; dst = s_wof; off = i - N4_X - N4_WQ - N4_WK;
    }
    float4 v = ((const float4*)src)[off];
    __half h[4];
    h[0] = __float2half(v.x); h[1] = __float2half(v.y);
    h[2] = __float2half(v.z); h[3] = __float2half(v.w);
    ((uint2*)dst)[off] = *(const uint2*)h;
}

// ---------------------------------------------------------------------------
// fp16 single-pass GEMM via mma.sync, 3-stage cp.async pipeline.
// MODE 0: Cout fp32 [M,E]  (Wout projection: A=s_af, W=s_wof)
// MODE 3: merged QKV: blockIdx.x selects Q / K / V target + weight matrix
// Epilogues write bf16 hi/lo Q,K ([B,H,N,D]) and V ([B,H,D,N]) for flash.
// ---------------------------------------------------------------------------
#define TILE_BYTES 8192            // 128 rows x 64B (32 fp16)
#define STAGE_BYTES (2 * TILE_BYTES)
#define GEMM_SMEM 67584            // max(3 stages = 48KB, epilogue 128*132*4)

__device__ __forceinline__ void load_chunk(
    uint32_t stage, const __half* Af, const __half* Wf,
    int m0, int wrow0, int k0, int tid)
{
#pragma unroll
    for (int t = 0; t < 2; ++t) {
        const int c = tid + t * 256;           // 0..511
        const int row = c >> 2;
        const int kc = c & 3;
        const uint32_t so = swz((uint32_t)(row * 64 + kc * 16));
        cp16(stage + so, Af + (size_t)(m0 + row) * EE + k0 + kc * 8);
        cp16(stage + TILE_BYTES + so, Wf + (size_t)(wrow0 + row) * EE + k0 + kc * 8);
    }
}

template <int MODE>
__global__ void __launch_bounds__(256) gemm_mma(
    const __half* __restrict__ Af,
    const __half* __restrict__ Wqf, const __half* __restrict__ Wkf,
    float* __restrict__ Cout)
{
    extern __shared__ char smem[];
    const uint32_t sb = smem_u32(smem);
    const int tid = threadIdx.x;
    const int lane = tid & 31;
    const int w = tid >> 5;
    const int wm = w >> 2;
    const int wn = w & 3;
    const int m0 = blockIdx.y * 128;
    const int n0 = blockIdx.x * 128;

    const __half* Wf;
    int wrow0, ek;
    if (MODE == 0) {
        Wf = Wqf; wrow0 = n0; ek = 3;
    } else {
        if (n0 < EE) { Wf = Wqf; wrow0 = n0; ek = 0; }
        else {
            Wf = Wkf; wrow0 = n0 - EE;
            ek = (wrow0 < EE) ? 1 : 2;
        }
    }

    float acc[4][4][4];
#pragma unroll
    for (int i = 0; i < 4; ++i)
#pragma unroll
        for (int j = 0; j < 4; ++j)
#pragma unroll
            for (int r = 0; r < 4; ++r) acc[i][j][r] = 0.0f;

    const int sel = lane >> 3;
    const int lrow8 = ((sel & 1) << 3) + (lane & 7);
    const int lkc = sel >> 1;

    const int nk = EE >> 5;     // 64
    load_chunk(sb + 0 * STAGE_BYTES, Af, Wf, m0, wrow0, 0, tid);
    cp_commit();
    load_chunk(sb + 1 * STAGE_BYTES, Af, Wf, m0, wrow0, 32, tid);
    cp_commit();

    int stg_idx = 0;
    for (int kt = 0; kt < nk; ++kt) {
        const uint32_t stage = sb + stg_idx * STAGE_BYTES;

        if (kt + 2 < nk) {
            int nidx = stg_idx + 2; if (nidx >= 3) nidx -= 3;
            load_chunk(sb + nidx * STAGE_BYTES, Af, Wf, m0, wrow0,
                       (kt + 2) << 5, tid);
            cp_commit();
            asm volatile("cp.async.wait_group 2;");
        } else if (kt + 1 < nk) {
            asm volatile("cp.async.wait_group 1;");
        } else {
            asm volatile("cp.async.wait_group 0;");
        }
        __syncthreads();

#pragma unroll
        for (int kk = 0; kk < 2; ++kk) {
            const int kchunk = kk * 2 + lkc;
            uint32_t af[4][4];
#pragma unroll
            for (int i = 0; i < 4; ++i) {
                const int r = wm * 64 + i * 16 + lrow8;
                const uint32_t off = swz((uint32_t)(r * 64 + kchunk * 16));
                ldmx4(af[i], stage + off);
            }
            uint32_t bf[2][4];
#pragma unroll
            for (int j2 = 0; j2 < 2; ++j2) {
                const int r = wn * 32 + j2 * 16 + lrow8;
                const uint32_t off = swz((uint32_t)(r * 64 + kchunk * 16));
                ldmx4(bf[j2], stage + TILE_BYTES + off);
            }
#pragma unroll
            for (int i = 0; i < 4; ++i) {
#pragma unroll
                for (int j = 0; j < 4; ++j) {
                    const int j2 = j >> 1, jo = j & 1;
                    mma16816h(acc[i][j], af[i], bf[j2][jo], bf[j2][2 + jo]);
                }
            }
        }
        __syncthreads();
        ++stg_idx; if (stg_idx >= 3) stg_idx = 0;
    }

    // ---- Epilogue ----
    float* Ss = (float*)smem;   // [128][132]
#pragma unroll
    for (int i = 0; i < 4; ++i) {
        const int r = wm * 64 + i * 16 + (lane >> 2);
#pragma unroll
        for (int j = 0; j < 4; ++j) {
            const int cc = wn * 32 + j * 8 + 2 * (lane & 3);
            Ss[r * 132 + cc]           = acc[i][j][0];
            Ss[r * 132 + cc + 1]       = acc[i][j][1];
            Ss[(r + 8) * 132 + cc]     = acc[i][j][2];
            Ss[(r + 8) * 132 + cc + 1] = acc[i][j][3];
        }
    }
    __syncthreads();

    const int b = m0 >> 11;
    const int nbase = m0 & (NN - 1);

    if (ek == 3) {
#pragma unroll
        for (int it = 0; it < 16; ++it) {
            const int f = it * 256 + tid;
            const int r = f >> 5;
            const int c4 = (f & 31) << 2;
            float4 v = *(const float4*)(Ss + r * 132 + c4);
            *(float4*)(Cout + (size_t)(m0 + r) * EE + n0 + c4) = v;
        }
    } else if (ek == 0 || ek == 1) {
        const int h = (wrow0 & (EE - 1)) >> 7;
        __nv_bfloat16* dh = (ek == 0 ? g_qh : g_kh) +
            ((size_t)(b * HH + h) * NN + nbase) * DD;
        __nv_bfloat16* dl = (ek == 0 ? g_ql : g_kl) +
            ((size_t)(b * HH + h) * NN + nbase) * DD;
#pragma unroll
        for (int it = 0; it < 16; ++it) {
            const int f = it * 256 + tid;
            const int r = f >> 5;
            const int c4 = (f & 31) << 2;
            float4 v = *(const float4*)(Ss + r * 132 + c4);
            float vv[4] = {v.x, v.y, v.z, v.w};
            __nv_bfloat16 hi[4], lo[4];
#pragma unroll
            for (int q = 0; q < 4; ++q) {
                hi[q] = __float2bfloat16(vv[q]);
                lo[q] = __float2bfloat16(vv[q] - __bfloat162float(hi[q]));
            }
            *(uint2*)(dh + (size_t)r * DD + c4) = *(const uint2*)hi;
            *(uint2*)(dl + (size_t)r * DD + c4) = *(const uint2*)lo;
        }
    } else {
        // V -> g_vth/g_vtl bf16 split, transposed [B,H,D,N]
        const int h2 = (wrow0 - EE) >> 7;
        const int col = tid >> 1;
        const int rh2 = tid & 1;
        const size_t dof = ((size_t)(b * HH + h2) * DD + col) * NN +
                           nbase + (rh2 << 6);
        __nv_bfloat16* dsth = g_vth + dof;
        __nv_bfloat16* dstl = g_vtl + dof;
#pragma unroll
        for (int i = 0; i < 16; ++i) {
            const int r = (rh2 << 6) + (i << 2);
            __nv_bfloat16 vh4[4], vl4[4];
#pragma unroll
            for (int q = 0; q < 4; ++q) {
                const float f = Ss[(r + q) * 132 + col];
                vh4[q] = __float2bfloat16(f);
                vl4[q] = __float2bfloat16(f - __bfloat162float(vh4[q]));
            }
            *(uint2*)(dsth + (i << 2)) = *(const uint2*)vh4;
            *(uint2*)(dstl + (i << 2)) = *(const uint2*)vl4;
        }
    }
}

// ---------------------------------------------------------------------------
// Flash attention v2 (proven 1693.7us schedule): mma.sync, 3-term bf16 splits
// for QK^T AND PV. Br=128 (8 warps x 16 rows), Bc=64, D=128.
// Epilogue now writes fp16 attn output to s_af [B,N,E].
// ---------------------------------------------------------------------------
#define FQ_BYTES 34816              // 128*272
#define FK_BYTES 17408              // 64*272
#define FV_BYTES 18432              // 128*144
#define FSTAGE (2 * FK_BYTES + 2 * FV_BYTES)        // 71680
#define FLASH2_SMEM (2 * FQ_BYTES + 2 * FSTAGE)     // 212992

__device__ __forceinline__ void load_kv(
    uint32_t stg, const __nv_bfloat16* Khg, const __nv_bfloat16* Klg,
    const __nv_bfloat16* Vhg, const __nv_bfloat16* Vlg, int j0, int tid)
{
#pragma unroll
    for (int t = 0; t < 4; ++t) {
        const int c = t * 256 + tid;        // 0..1023
        const int row = c >> 4, ch = c & 15;
        const uint32_t dst = stg + row * 272 + ch * 16;
        const size_t src = (size_t)(j0 + row) * DD + ch * 8;
        cp16(dst, Khg + src);
        cp16(dst + FK_BYTES, Klg + src);
    }
#pragma unroll
    for (int t = 0; t < 4; ++t) {
        const int c = t * 256 + tid;        // 0..1023
        const int drow = c >> 3, ch = c & 7;
        const uint32_t dst = stg + 2 * FK_BYTES + drow * 144 + ch * 16;
        const size_t src = (size_t)drow * NN + j0 + ch * 8;
        cp16(dst, Vhg + src);
        cp16(dst + FV_BYTES, Vlg + src);
    }
}

__global__ void __launch_bounds__(256, 1) flash_mma()
{
    extern __shared__ char smc[];
    const uint32_t sb = smem_u32(smc);
    const int tid = threadIdx.x;
    const int lane = tid & 31;
    const int w = tid >> 5;
    const int bh = blockIdx.y;
    const int b = bh >> 4, h = bh & (HH - 1);
    const int qt = (gridDim.x - 1) - blockIdx.x;   // long tiles first
    const int i0 = qt * 128;

    const __nv_bfloat16* Qhg = g_qh + (size_t)bh * NN * DD;
    const __nv_bfloat16* Qlg = g_ql + (size_t)bh * NN * DD;
    const __nv_bfloat16* Khg = g_kh + (size_t)bh * NN * DD;
    const __nv_bfloat16* Klg = g_kl + (size_t)bh * NN * DD;
    const __nv_bfloat16* Vhg = g_vth + (size_t)bh * DD * NN;
    const __nv_bfloat16* Vlg = g_vtl + (size_t)bh * DD * NN;

    // Q tiles (hi+lo)
#pragma unroll
    for (int t = 0; t < 8; ++t) {
        const int c = t * 256 + tid;        // 0..2047
        const int row = c >> 4, ch = c & 15;
        const uint32_t dst = sb + row * 272 + ch * 16;
        const size_t src = (size_t)(i0 + row) * DD + ch * 8;
        cp16(dst, Qhg + src);
        cp16(dst + FQ_BYTES, Qlg + src);
    }
    load_kv(sb + 2 * FQ_BYTES, Khg, Klg, Vhg, Vlg, 0, tid);
    cp_commit();

    const int nj = 2 * qt + 2;
    float m_[2] = {-1e30f, -1e30f}, l_[2] = {0.0f, 0.0f};
    float O[16][4];
#pragma unroll
    for (int nt = 0; nt < 16; ++nt)
#pragma unroll
        for (int r = 0; r < 4; ++r) O[nt][r] = 0.0f;

    const int r0 = w * 16 + (lane >> 2);

    for (int jt = 0; jt < nj; ++jt) {
        const uint32_t stg = sb + 2 * FQ_BYTES + (jt & 1) * FSTAGE;
        if (jt + 1 < nj) {
            load_kv(sb + 2 * FQ_BYTES + ((jt + 1) & 1) * FSTAGE,
                    Khg, Klg, Vhg, Vlg, (jt + 1) * 64, tid);
            cp_commit();
            asm volatile("cp.async.wait_group 1;");
        } else {
            asm volatile("cp.async.wait_group 0;");
        }
        __syncthreads();

        // ---- S = Q K^T (3-term split) ----
        float S[8][4];
#pragma unroll
        for (int nt = 0; nt < 8; ++nt)
#pragma unroll
            for (int r = 0; r < 4; ++r) S[nt][r] = 0.0f;

        const int lrA = w * 16 + ((lane >> 3) & 1) * 8 + (lane & 7);
        const int cA16 = (lane >> 4) & 1;
        const int lrB = ((lane >> 4) & 1) * 8 + (lane & 7);
        const int cB16 = (lane >> 3) & 1;

#pragma unroll
        for (int ks = 0; ks < 8; ++ks) {
            uint32_t ah[4], al[4];
            const uint32_t qoff = lrA * 272 + ks * 32 + cA16 * 16;
            ldmx4(ah, sb + qoff);
            ldmx4(al, sb + FQ_BYTES + qoff);
#pragma unroll
            for (int jn2 = 0; jn2 < 4; ++jn2) {
                uint32_t bhf[4], blf[4];
                const uint32_t koff = (jn2 * 16 + lrB) * 272 + ks * 32 + cB16 * 16;
                ldmx4(bhf, stg + koff);
                ldmx4(blf, stg + FK_BYTES + koff);
                mma16816(S[2 * jn2],     ah, bhf[0], bhf[1]);
                mma16816(S[2 * jn2],     al, bhf[0], bhf[1]);
                mma16816(S[2 * jn2],     ah, blf[0], blf[1]);
                mma16816(S[2 * jn2 + 1], ah, bhf[2], bhf[3]);
                mma16816(S[2 * jn2 + 1], al, bhf[2], bhf[3]);
                mma16816(S[2 * jn2 + 1], ah, blf[2], blf[3]);
            }
        }

        // ---- scale + causal mask ----
        const int j0 = jt * 64;
#pragma unroll
        for (int nt = 0; nt < 8; ++nt)
#pragma unroll
            for (int r = 0; r < 4; ++r) S[nt][r] *= SCALE;

        if (jt >= nj - 2) {
#pragma unroll
            for (int nt = 0; nt < 8; ++nt) {
                const int jc = j0 + nt * 8 + (lane & 3) * 2;
#pragma unroll
                for (int r = 0; r < 4; ++r) {
                    const int i = i0 + r0 + (r >> 1) * 8;
                    if (jc + (r & 1) > i) S[nt][r] = -1e30f;
                }
            }
        }

        // ---- online softmax (rows: r0, r0+8) ----
        float rm0 = -1e30f, rm1 = -1e30f;
#pragma unroll
        for (int nt = 0; nt < 8; ++nt) {
            rm0 = fmaxf(rm0, fmaxf(S[nt][0], S[nt][1]));
            rm1 = fmaxf(rm1, fmaxf(S[nt][2], S[nt][3]));
        }
        rm0 = fmaxf(rm0, __shfl_xor_sync(0xffffffffu, rm0, 1));
        rm0 = fmaxf(rm0, __shfl_xor_sync(0xffffffffu, rm0, 2));
        rm1 = fmaxf(rm1, __shfl_xor_sync(0xffffffffu, rm1, 1));
        rm1 = fmaxf(rm1, __shfl_xor_sync(0xffffffffu, rm1, 2));

        const float mn0 = fmaxf(m_[0], rm0);
        const float mn1 = fmaxf(m_[1], rm1);
        const float al0 = __expf(m_[0] - mn0);
        const float al1 = __expf(m_[1] - mn1);
        float rs0 = 0.0f, rs1 = 0.0f;
#pragma unroll
        for (int nt = 0; nt < 8; ++nt) {
            S[nt][0] = __expf(S[nt][0] - mn0);
            S[nt][1] = __expf(S[nt][1] - mn0);
            S[nt][2] = __expf(S[nt][2] - mn1);
            S[nt][3] = __expf(S[nt][3] - mn1);
            rs0 += S[nt][0] + S[nt][1];
            rs1 += S[nt][2] + S[nt][3];
        }
        rs0 += __shfl_xor_sync(0xffffffffu, rs0, 1);
        rs0 += __shfl_xor_sync(0xffffffffu, rs0, 2);
        rs1 += __shfl_xor_sync(0xffffffffu, rs1, 1);
        rs1 += __shfl_xor_sync(0xffffffffu, rs1, 2);

        l_[0] = l_[0] * al0 + rs0;
        l_[1] = l_[1] * al1 + rs1;
        m_[0] = mn0; m_[1] = mn1;

#pragma unroll
        for (int nt = 0; nt < 16; ++nt) {
            O[nt][0] *= al0; O[nt][1] *= al0;
            O[nt][2] *= al1; O[nt][3] *= al1;
        }

        // ---- O += P V  (3-term split: Ph*Vh + Pl*Vh + Ph*Vl) ----
#pragma unroll
        for (int kc = 0; kc < 4; ++kc) {
            float p00 = S[2 * kc][0],     p01 = S[2 * kc][1];
            float p02 = S[2 * kc][2],     p03 = S[2 * kc][3];
            float p10 = S[2 * kc + 1][0], p11 = S[2 * kc + 1][1];
            float p12 = S[2 * kc + 1][2], p13 = S[2 * kc + 1][3];
            uint32_t pah[4], pal[4];
            pah[0] = packbf(p00, p01);
            pah[1] = packbf(p02, p03);
            pah[2] = packbf(p10, p11);
            pah[3] = packbf(p12, p13);
            {
                __nv_bfloat162 t0 = *(__nv_bfloat162*)&pah[0];
                __nv_bfloat162 t1 = *(__nv_bfloat162*)&pah[1];
                __nv_bfloat162 t2 = *(__nv_bfloat162*)&pah[2];
                __nv_bfloat162 t3 = *(__nv_bfloat162*)&pah[3];
                pal[0] = packbf(p00 - __bfloat162float(t0.x), p01 - __bfloat162float(t0.y));
                pal[1] = packbf(p02 - __bfloat162float(t1.x), p03 - __bfloat162float(t1.y));
                pal[2] = packbf(p10 - __bfloat162float(t2.x), p11 - __bfloat162float(t2.y));
                pal[3] = packbf(p12 - __bfloat162float(t3.x), p13 - __bfloat162float(t3.y));
            }
#pragma unroll
            for (int dt2 = 0; dt2 < 8; ++dt2) {
                uint32_t vbh[4], vbl[4];
                const uint32_t voff = 2 * FK_BYTES +
                    (dt2 * 16 + lrB) * 144 + kc * 32 + cB16 * 16;
                ldmx4(vbh, stg + voff);
                ldmx4(vbl, stg + FV_BYTES + voff);
                mma16816(O[2 * dt2],     pah, vbh[0], vbh[1]);
                mma16816(O[2 * dt2],     pal, vbh[0], vbh[1]);
                mma16816(O[2 * dt2],     pah, vbl[0], vbl[1]);
                mma16816(O[2 * dt2 + 1], pah, vbh[2], vbh[3]);
                mma16816(O[2 * dt2 + 1], pal, vbh[2], vbh[3]);
                mma16816(O[2 * dt2 + 1], pah, vbl[2], vbl[3]);
            }
        }
        __syncthreads();
    }

    // ---- epilogue: normalize, fp16 store to s_af [B,N,E] ----
#pragma unroll
    for (int rh = 0; rh < 2; ++rh) {
        const int i = i0 + r0 + rh * 8;
        const float inv = 1.0f / l_[rh];
#pragma unroll
        for (int nt = 0; nt < 16; ++nt) {
            const int d = nt * 8 + (lane & 3) * 2;
            const size_t idx = ((size_t)(b * NN + i)) * EE + h * DD + d;
            __half hp[2];
            hp[0] = __float2half(O[nt][2 * rh] * inv);
            hp[1] = __float2half(O[nt][2 * rh + 1] * inv);
            *(uint32_t*)(s_af + idx) = *(const uint32_t*)hp;
        }
    }
}

// ---------------------------------------------------------------------------
// Launch
// ---------------------------------------------------------------------------
extern "C" void kernel_launch(void* const* d_in, const int* in_sizes, int n_in,
                              void* d_out, int out_size)
{
    const float* x    = (const float*)d_in[0];
    const float* Wq   = (const float*)d_in[1];
    const float* Wkv  = (const float*)d_in[2];
    const float* Wout = (const float*)d_in[3];
    float* out = (float*)d_out;

    void *xf, *wqf, *wkf, *wof, *af;
    cudaGetSymbolAddress(&xf, s_xf);
    cudaGetSymbolAddress(&wqf, s_wqf);
    cudaGetSymbolAddress(&wkf, s_wkf);
    cudaGetSymbolAddress(&wof, s_wof);
    cudaGetSymbolAddress(&af, s_af);

    // One merged convert launch for all four inputs
    split_all_kernel<<<(N4_TOT + 255) / 256, 256>>>(x, Wq, Wkv, Wout);

    cudaFuncSetAttribute(gemm_mma<0>, cudaFuncAttributeMaxDynamicSharedMemorySize, GEMM_SMEM);
    cudaFuncSetAttribute(gemm_mma<3>, cudaFuncAttributeMaxDynamicSharedMemorySize, GEMM_SMEM);

    // Merged QKV projection: grid.x covers [Q | K | V] column tiles
    gemm_mma<3><<<dim3(3 * EE / 128, MTOT / 128), 256, GEMM_SMEM>>>(
        (const __half*)xf, (const __half*)wqf, (const __half*)wkf, nullptr);

    cudaFuncSetAttribute(flash_mma, cudaFuncAttributeMaxDynamicSharedMemorySize,
                         FLASH2_SMEM);
    flash_mma<<<dim3(NN / 128, BB * HH), 256, FLASH2_SMEM>>>();

    // Output projection
    gemm_mma<0><<<dim3(EE / 128, MTOT / 128), 256, GEMM_SMEM>>>(
        (const __half*)af, (const __half*)wof, nullptr, out);
}

// round 14
// speedup vs baseline: 2.7661x; 1.2973x over previous
#include <cuda_runtime.h>
#include <cuda_bf16.h>
#include <cuda_fp16.h>
#include <cstdint>

// Problem constants
#define BB 2
#define NN 2048
#define EE 2048
#define HH 16
#define DD 128
#define MTOT (BB * NN)
#define SCALE 0.08838834764831843f

// ---------------------------------------------------------------------------
// Device scratch (allocation-free rule)
// ---------------------------------------------------------------------------
__device__ __half g_qf[(size_t)BB * HH * NN * DD];   // Q fp16 [B,H,N,D]
__device__ __half g_kf[(size_t)BB * HH * NN * DD];   // K fp16 [B,H,N,D]
__device__ __half g_vtf[(size_t)BB * HH * DD * NN];  // V fp16 [B,H,D,N]

__device__ __half s_xf[8388608];    // x    fp16 [M,K]
__device__ __half s_wqf[4194304];   // Wq   fp16 [E,K]
__device__ __half s_wkf[8388608];   // Wkv  fp16 [2E,K]
__device__ __half s_wof[4194304];   // Wout fp16 [E,K]
__device__ __half s_af[8388608];    // attn fp16 [B,N,E]

// ---------------------------------------------------------------------------
// Helpers
// ---------------------------------------------------------------------------
__device__ __forceinline__ uint32_t smem_u32(const void* p) {
    uint32_t a;
    asm("{ .reg .u64 t; cvta.to.shared.u64 t, %1; cvt.u32.u64 %0, t; }"
        : "=r"(a) : "l"(p));
    return a;
}
__device__ __forceinline__ void cp16(uint32_t dst, const void* src) {
    asm volatile("cp.async.cg.shared.global [%0], [%1], 16;"
                 :: "r"(dst), "l"(src));
}
__device__ __forceinline__ void cp_commit() {
    asm volatile("cp.async.commit_group;");
}
__device__ __forceinline__ uint32_t swz(uint32_t off) {   // SW64 for 64B rows
    return off ^ ((off >> 3) & 0x30);
}
__device__ __forceinline__ void ldmx4(uint32_t* f, uint32_t addr) {
    asm volatile("ldmatrix.sync.aligned.m8n8.x4.shared.b16 {%0,%1,%2,%3}, [%4];"
                 : "=r"(f[0]), "=r"(f[1]), "=r"(f[2]), "=r"(f[3]) : "r"(addr));
}
// fp16 MMA
__device__ __forceinline__ void mma16816h(float* c, const uint32_t* a,
                                          uint32_t b0, uint32_t b1) {
    asm volatile(
        "mma.sync.aligned.m16n8k16.row.col.f32.f16.f16.f32 "
        "{%0,%1,%2,%3}, {%4,%5,%6,%7}, {%8,%9}, {%0,%1,%2,%3};"
        : "+f"(c[0]), "+f"(c[1]), "+f"(c[2]), "+f"(c[3])
        : "r"(a[0]), "r"(a[1]), "r"(a[2]), "r"(a[3]), "r"(b0), "r"(b1));
}
__device__ __forceinline__ uint32_t packhf(float a, float b) {
    __half2 t = __floats2half2_rn(a, b);
    return *(uint32_t*)&t;
}

// ---------------------------------------------------------------------------
// Merged convert kernel: all four fp32 inputs -> fp16 in one launch
// ---------------------------------------------------------------------------
#define N4_X  2097152
#define N4_WQ 1048576
#define N4_WK 2097152
#define N4_WO 1048576
#define N4_TOT (N4_X + N4_WQ + N4_WK + N4_WO)   // 6291456

__global__ __launch_bounds__(256) void split_all_kernel(
    const float* __restrict__ x, const float* __restrict__ wq,
    const float* __restrict__ wk, const float* __restrict__ wo)
{
    int i = blockIdx.x * blockDim.x + threadIdx.x;
    if (i >= N4_TOT) return;
    const float* src;
    __half* dst;
    int off;
    if (i < N4_X) {
        src = x; dst = s_xf; off = i;
    } else if (i < N4_X + N4_WQ) {
        src = wq; dst = s_wqf; off = i - N4_X;
    } else if (i < N4_X + N4_WQ + N4_WK) {
        src = wk; dst = s_wkf; off = i - N4_X - N4_WQ;
    } else {
        src = wo; dst = s_wof; off = i - N4_X - N4_WQ - N4_WK;
    }
    float4 v = ((const float4*)src)[off];
    __half h[4];
    h[0] = __float2half(v.x); h[1] = __float2half(v.y);
    h[2] = __float2half(v.z); h[3] = __float2half(v.w);
    ((uint2*)dst)[off] = *(const uint2*)h;
}

// ---------------------------------------------------------------------------
// fp16 single-pass GEMM via mma.sync, 3-stage cp.async pipeline.
// MODE 0: Cout fp32 [M,E]  (Wout projection: A=s_af, W=s_wof)
// MODE 3: merged QKV: blockIdx.x selects Q / K / V target + weight matrix
// Epilogues write fp16 Q,K ([B,H,N,D]) and V ([B,H,D,N]) for flash.
// ---------------------------------------------------------------------------
#define TILE_BYTES 8192            // 128 rows x 64B (32 fp16)
#define STAGE_BYTES (2 * TILE_BYTES)
#define GEMM_SMEM 67584            // max(3 stages = 48KB, epilogue 128*132*4)

__device__ __forceinline__ void load_chunk(
    uint32_t stage, const __half* Af, const __half* Wf,
    int m0, int wrow0, int k0, int tid)
{
#pragma unroll
    for (int t = 0; t < 2; ++t) {
        const int c = tid + t * 256;           // 0..511
        const int row = c >> 2;
        const int kc = c & 3;
        const uint32_t so = swz((uint32_t)(row * 64 + kc * 16));
        cp16(stage + so, Af + (size_t)(m0 + row) * EE + k0 + kc * 8);
        cp16(stage + TILE_BYTES + so, Wf + (size_t)(wrow0 + row) * EE + k0 + kc * 8);
    }
}

template <int MODE>
__global__ void __launch_bounds__(256) gemm_mma(
    const __half* __restrict__ Af,
    const __half* __restrict__ Wqf, const __half* __restrict__ Wkf,
    float* __restrict__ Cout)
{
    extern __shared__ char smem[];
    const uint32_t sb = smem_u32(smem);
    const int tid = threadIdx.x;
    const int lane = tid & 31;
    const int w = tid >> 5;
    const int wm = w >> 2;
    const int wn = w & 3;
    const int m0 = blockIdx.y * 128;
    const int n0 = blockIdx.x * 128;

    const __half* Wf;
    int wrow0, ek;
    if (MODE == 0) {
        Wf = Wqf; wrow0 = n0; ek = 3;
    } else {
        if (n0 < EE) { Wf = Wqf; wrow0 = n0; ek = 0; }
        else {
            Wf = Wkf; wrow0 = n0 - EE;
            ek = (wrow0 < EE) ? 1 : 2;
        }
    }

    float acc[4][4][4];
#pragma unroll
    for (int i = 0; i < 4; ++i)
#pragma unroll
        for (int j = 0; j < 4; ++j)
#pragma unroll
            for (int r = 0; r < 4; ++r) acc[i][j][r] = 0.0f;

    const int sel = lane >> 3;
    const int lrow8 = ((sel & 1) << 3) + (lane & 7);
    const int lkc = sel >> 1;

    const int nk = EE >> 5;     // 64
    load_chunk(sb + 0 * STAGE_BYTES, Af, Wf, m0, wrow0, 0, tid);
    cp_commit();
    load_chunk(sb + 1 * STAGE_BYTES, Af, Wf, m0, wrow0, 32, tid);
    cp_commit();

    int stg_idx = 0;
    for (int kt = 0; kt < nk; ++kt) {
        const uint32_t stage = sb + stg_idx * STAGE_BYTES;

        if (kt + 2 < nk) {
            int nidx = stg_idx + 2; if (nidx >= 3) nidx -= 3;
            load_chunk(sb + nidx * STAGE_BYTES, Af, Wf, m0, wrow0,
                       (kt + 2) << 5, tid);
            cp_commit();
            asm volatile("cp.async.wait_group 2;");
        } else if (kt + 1 < nk) {
            asm volatile("cp.async.wait_group 1;");
        } else {
            asm volatile("cp.async.wait_group 0;");
        }
        __syncthreads();

#pragma unroll
        for (int kk = 0; kk < 2; ++kk) {
            const int kchunk = kk * 2 + lkc;
            uint32_t af[4][4];
#pragma unroll
            for (int i = 0; i < 4; ++i) {
                const int r = wm * 64 + i * 16 + lrow8;
                const uint32_t off = swz((uint32_t)(r * 64 + kchunk * 16));
                ldmx4(af[i], stage + off);
            }
            uint32_t bf[2][4];
#pragma unroll
            for (int j2 = 0; j2 < 2; ++j2) {
                const int r = wn * 32 + j2 * 16 + lrow8;
                const uint32_t off = swz((uint32_t)(r * 64 + kchunk * 16));
                ldmx4(bf[j2], stage + TILE_BYTES + off);
            }
#pragma unroll
            for (int i = 0; i < 4; ++i) {
#pragma unroll
                for (int j = 0; j < 4; ++j) {
                    const int j2 = j >> 1, jo = j & 1;
                    mma16816h(acc[i][j], af[i], bf[j2][jo], bf[j2][2 + jo]);
                }
            }
        }
        __syncthreads();
        ++stg_idx; if (stg_idx >= 3) stg_idx = 0;
    }

    // ---- Epilogue ----
    float* Ss = (float*)smem;   // [128][132]
#pragma unroll
    for (int i = 0; i < 4; ++i) {
        const int r = wm * 64 + i * 16 + (lane >> 2);
#pragma unroll
        for (int j = 0; j < 4; ++j) {
            const int cc = wn * 32 + j * 8 + 2 * (lane & 3);
            Ss[r * 132 + cc]           = acc[i][j][0];
            Ss[r * 132 + cc + 1]       = acc[i][j][1];
            Ss[(r + 8) * 132 + cc]     = acc[i][j][2];
            Ss[(r + 8) * 132 + cc + 1] = acc[i][j][3];
        }
    }
    __syncthreads();

    const int b = m0 >> 11;
    const int nbase = m0 & (NN - 1);

    if (ek == 3) {
#pragma unroll
        for (int it = 0; it < 16; ++it) {
            const int f = it * 256 + tid;
            const int r = f >> 5;
            const int c4 = (f & 31) << 2;
            float4 v = *(const float4*)(Ss + r * 132 + c4);
            *(float4*)(Cout + (size_t)(m0 + r) * EE + n0 + c4) = v;
        }
    } else if (ek == 0 || ek == 1) {
        const int h = wrow0 >> 7;
        __half* dq = (ek == 0 ? g_qf : g_kf) +
            ((size_t)(b * HH + h) * NN + nbase) * DD;
#pragma unroll
        for (int it = 0; it < 16; ++it) {
            const int f = it * 256 + tid;
            const int r = f >> 5;
            const int c4 = (f & 31) << 2;
            float4 v = *(const float4*)(Ss + r * 132 + c4);
            __half hq[4];
            hq[0] = __float2half(v.x); hq[1] = __float2half(v.y);
            hq[2] = __float2half(v.z); hq[3] = __float2half(v.w);
            *(uint2*)(dq + (size_t)r * DD + c4) = *(const uint2*)hq;
        }
    } else {
        // V -> g_vtf fp16, transposed [B,H,D,N]
        const int h2 = (wrow0 - EE) >> 7;
        const int col = tid >> 1;
        const int rh2 = tid & 1;
        __half* dst = g_vtf + ((size_t)(b * HH + h2) * DD + col) * NN +
                      nbase + (rh2 << 6);
#pragma unroll
        for (int i = 0; i < 16; ++i) {
            const int r = (rh2 << 6) + (i << 2);
            __half v4[4];
            v4[0] = __float2half(Ss[(r + 0) * 132 + col]);
            v4[1] = __float2half(Ss[(r + 1) * 132 + col]);
            v4[2] = __float2half(Ss[(r + 2) * 132 + col]);
            v4[3] = __float2half(Ss[(r + 3) * 132 + col]);
            *(uint2*)(dst + (i << 2)) = *(const uint2*)v4;
        }
    }
}

// ---------------------------------------------------------------------------
// Flash attention v3: single-pass fp16 mma.sync for QK^T and PV.
// Br=128 (8 warps x 16 rows), Bc=64, D=128. Same proven schedule/addressing,
// lo-paths removed. Smem 104KB -> 2 CTAs/SM.
// Smem: Q [128x272B] | 2 stages of {K 64x272B; Vt 128x144B}
// ---------------------------------------------------------------------------
#define FQ_BYTES 34816              // 128*272
#define FK_BYTES 17408              // 64*272
#define FV_BYTES 18432              // 128*144
#define FSTAGE (FK_BYTES + FV_BYTES)                // 35840
#define FLASH2_SMEM (FQ_BYTES + 2 * FSTAGE)         // 106496

__device__ __forceinline__ void load_kv(
    uint32_t stg, const __half* Kf, const __half* Vf, int j0, int tid)
{
#pragma unroll
    for (int t = 0; t < 4; ++t) {
        const int c = t * 256 + tid;        // 0..1023
        const int row = c >> 4, ch = c & 15;
        cp16(stg + row * 272 + ch * 16,
             Kf + (size_t)(j0 + row) * DD + ch * 8);
    }
#pragma unroll
    for (int t = 0; t < 4; ++t) {
        const int c = t * 256 + tid;        // 0..1023
        const int drow = c >> 3, ch = c & 7;
        cp16(stg + FK_BYTES + drow * 144 + ch * 16,
             Vf + (size_t)drow * NN + j0 + ch * 8);
    }
}

__global__ void __launch_bounds__(256, 2) flash_mma()
{
    extern __shared__ char smc[];
    const uint32_t sb = smem_u32(smc);
    const int tid = threadIdx.x;
    const int lane = tid & 31;
    const int w = tid >> 5;
    const int bh = blockIdx.y;
    const int b = bh >> 4, h = bh & (HH - 1);
    const int qt = (gridDim.x - 1) - blockIdx.x;   // long tiles first
    const int i0 = qt * 128;

    const __half* Qf = g_qf + (size_t)bh * NN * DD;
    const __half* Kf = g_kf + (size_t)bh * NN * DD;
    const __half* Vf = g_vtf + (size_t)bh * DD * NN;

    // Q tile
#pragma unroll
    for (int t = 0; t < 8; ++t) {
        const int c = t * 256 + tid;        // 0..2047
        const int row = c >> 4, ch = c & 15;
        cp16(sb + row * 272 + ch * 16,
             Qf + (size_t)(i0 + row) * DD + ch * 8);
    }
    load_kv(sb + FQ_BYTES, Kf, Vf, 0, tid);
    cp_commit();

    const int nj = 2 * qt + 2;
    float m_[2] = {-1e30f, -1e30f}, l_[2] = {0.0f, 0.0f};
    float O[16][4];
#pragma unroll
    for (int nt = 0; nt < 16; ++nt)
#pragma unroll
        for (int r = 0; r < 4; ++r) O[nt][r] = 0.0f;

    const int r0 = w * 16 + (lane >> 2);

    for (int jt = 0; jt < nj; ++jt) {
        const uint32_t stg = sb + FQ_BYTES + (jt & 1) * FSTAGE;
        if (jt + 1 < nj) {
            load_kv(sb + FQ_BYTES + ((jt + 1) & 1) * FSTAGE,
                    Kf, Vf, (jt + 1) * 64, tid);
            cp_commit();
            asm volatile("cp.async.wait_group 1;");
        } else {
            asm volatile("cp.async.wait_group 0;");
        }
        __syncthreads();

        // ---- S = Q K^T (single-pass fp16) ----
        float S[8][4];
#pragma unroll
        for (int nt = 0; nt < 8; ++nt)
#pragma unroll
            for (int r = 0; r < 4; ++r) S[nt][r] = 0.0f;

        const int lrA = w * 16 + ((lane >> 3) & 1) * 8 + (lane & 7);
        const int cA16 = (lane >> 4) & 1;
        const int lrB = ((lane >> 4) & 1) * 8 + (lane & 7);
        const int cB16 = (lane >> 3) & 1;

#pragma unroll
        for (int ks = 0; ks < 8; ++ks) {
            uint32_t aq[4];
            ldmx4(aq, sb + lrA * 272 + ks * 32 + cA16 * 16);
#pragma unroll
            for (int jn2 = 0; jn2 < 4; ++jn2) {
                uint32_t bk[4];
                ldmx4(bk, stg + (jn2 * 16 + lrB) * 272 + ks * 32 + cB16 * 16);
                mma16816h(S[2 * jn2],     aq, bk[0], bk[1]);
                mma16816h(S[2 * jn2 + 1], aq, bk[2], bk[3]);
            }
        }

        // ---- scale + causal mask ----
        const int j0 = jt * 64;
#pragma unroll
        for (int nt = 0; nt < 8; ++nt)
#pragma unroll
            for (int r = 0; r < 4; ++r) S[nt][r] *= SCALE;

        if (jt >= nj - 2) {
#pragma unroll
            for (int nt = 0; nt < 8; ++nt) {
                const int jc = j0 + nt * 8 + (lane & 3) * 2;
#pragma unroll
                for (int r = 0; r < 4; ++r) {
                    const int i = i0 + r0 + (r >> 1) * 8;
                    if (jc + (r & 1) > i) S[nt][r] = -1e30f;
                }
            }
        }

        // ---- online softmax (rows: r0, r0+8) ----
        float rm0 = -1e30f, rm1 = -1e30f;
#pragma unroll
        for (int nt = 0; nt < 8; ++nt) {
            rm0 = fmaxf(rm0, fmaxf(S[nt][0], S[nt][1]));
            rm1 = fmaxf(rm1, fmaxf(S[nt][2], S[nt][3]));
        }
        rm0 = fmaxf(rm0, __shfl_xor_sync(0xffffffffu, rm0, 1));
        rm0 = fmaxf(rm0, __shfl_xor_sync(0xffffffffu, rm0, 2));
        rm1 = fmaxf(rm1, __shfl_xor_sync(0xffffffffu, rm1, 1));
        rm1 = fmaxf(rm1, __shfl_xor_sync(0xffffffffu, rm1, 2));

        const float mn0 = fmaxf(m_[0], rm0);
        const float mn1 = fmaxf(m_[1], rm1);
        const float al0 = __expf(m_[0] - mn0);
        const float al1 = __expf(m_[1] - mn1);
        float rs0 = 0.0f, rs1 = 0.0f;
#pragma unroll
        for (int nt = 0; nt < 8; ++nt) {
            S[nt][0] = __expf(S[nt][0] - mn0);
            S[nt][1] = __expf(S[nt][1] - mn0);
            S[nt][2] = __expf(S[nt][2] - mn1);
            S[nt][3] = __expf(S[nt][3] - mn1);
            rs0 += S[nt][0] + S[nt][1];
            rs1 += S[nt][2] + S[nt][3];
        }
        rs0 += __shfl_xor_sync(0xffffffffu, rs0, 1);
        rs0 += __shfl_xor_sync(0xffffffffu, rs0, 2);
        rs1 += __shfl_xor_sync(0xffffffffu, rs1, 1);
        rs1 += __shfl_xor_sync(0xffffffffu, rs1, 2);

        l_[0] = l_[0] * al0 + rs0;
        l_[1] = l_[1] * al1 + rs1;
        m_[0] = mn0; m_[1] = mn1;

#pragma unroll
        for (int nt = 0; nt < 16; ++nt) {
            O[nt][0] *= al0; O[nt][1] *= al0;
            O[nt][2] *= al1; O[nt][3] *= al1;
        }

        // ---- O += P V  (single-pass fp16) ----
#pragma unroll
        for (int kc = 0; kc < 4; ++kc) {
            uint32_t pa[4];
            pa[0] = packhf(S[2 * kc][0],     S[2 * kc][1]);
            pa[1] = packhf(S[2 * kc][2],     S[2 * kc][3]);
            pa[2] = packhf(S[2 * kc + 1][0], S[2 * kc + 1][1]);
            pa[3] = packhf(S[2 * kc + 1][2], S[2 * kc + 1][3]);
#pragma unroll
            for (int dt2 = 0; dt2 < 8; ++dt2) {
                uint32_t vb[4];
                ldmx4(vb, stg + FK_BYTES +
                          (dt2 * 16 + lrB) * 144 + kc * 32 + cB16 * 16);
                mma16816h(O[2 * dt2],     pa, vb[0], vb[1]);
                mma16816h(O[2 * dt2 + 1], pa, vb[2], vb[3]);
            }
        }
        __syncthreads();
    }

    // ---- epilogue: normalize, fp16 store to s_af [B,N,E] ----
#pragma unroll
    for (int rh = 0; rh < 2; ++rh) {
        const int i = i0 + r0 + rh * 8;
        const float inv = 1.0f / l_[rh];
#pragma unroll
        for (int nt = 0; nt < 16; ++nt) {
            const int d = nt * 8 + (lane & 3) * 2;
            const size_t idx = ((size_t)(b * NN + i)) * EE + h * DD + d;
            __half hp[2];
            hp[0] = __float2half(O[nt][2 * rh] * inv);
            hp[1] = __float2half(O[nt][2 * rh + 1] * inv);
            *(uint32_t*)(s_af + idx) = *(const uint32_t*)hp;
        }
    }
}

// ---------------------------------------------------------------------------
// Launch
// ---------------------------------------------------------------------------
extern "C" void kernel_launch(void* const* d_in, const int* in_sizes, int n_in,
                              void* d_out, int out_size)
{
    const float* x    = (const float*)d_in[0];
    const float* Wq   = (const float*)d_in[1];
    const float* Wkv  = (const float*)d_in[2];
    const float* Wout = (const float*)d_in[3];
    float* out = (float*)d_out;

    void *xf, *wqf, *wkf, *wof, *af;
    cudaGetSymbolAddress(&xf, s_xf);
    cudaGetSymbolAddress(&wqf, s_wqf);
    cudaGetSymbolAddress(&wkf, s_wkf);
    cudaGetSymbolAddress(&wof, s_wof);
    cudaGetSymbolAddress(&af, s_af);

    // One merged convert launch for all four inputs
    split_all_kernel<<<(N4_TOT + 255) / 256, 256>>>(x, Wq, Wkv, Wout);

    cudaFuncSetAttribute(gemm_mma<0>, cudaFuncAttributeMaxDynamicSharedMemorySize, GEMM_SMEM);
    cudaFuncSetAttribute(gemm_mma<3>, cudaFuncAttributeMaxDynamicSharedMemorySize, GEMM_SMEM);

    // Merged QKV projection: grid.x covers [Q | K | V] column tiles
    gemm_mma<3><<<dim3(3 * EE / 128, MTOT / 128), 256, GEMM_SMEM>>>(
        (const __half*)xf, (const __half*)wqf, (const __half*)wkf, nullptr);

    cudaFuncSetAttribute(flash_mma, cudaFuncAttributeMaxDynamicSharedMemorySize,
                         FLASH2_SMEM);
    flash_mma<<<dim3(NN / 128, BB * HH), 256, FLASH2_SMEM>>>();

    // Output projection
    gemm_mma<0><<<dim3(EE / 128, MTOT / 128), 256, GEMM_SMEM>>>(
        (const __half*)af, (const __half*)wof, nullptr, out);
}